// round 2
// baseline (speedup 1.0000x reference)
#include <cuda_runtime.h>
#include <math.h>
#include <stdint.h>
#include <stddef.h>

#define N_NODES 131072
#define E_EDGES 2097152
#define B_PAIRS 4096
#define R_REL   5
#define L_LAYERS 4
#define T_STEPS 4096

// ---------------- device scratch (static globals; no runtime allocation) ----
static __device__ float g_relfeat[(size_t)N_NODES * R_REL * 32];  // 80 MB
static __device__ float g_agg[(size_t)N_NODES * 32];              // 16 MB
static __device__ float g_states[(size_t)N_NODES * 128];          // 64 MB
static __device__ int   g_cnt[(size_t)N_NODES * R_REL];           // 2.5 MB
static __device__ float g_weff[L_LAYERS * 32 * 192];              // 96 KB
static __device__ float g_z [(size_t)B_PAIRS * 256];              // 4 MB
static __device__ float g_h1[(size_t)B_PAIRS * 256];              // 4 MB
static __device__ float g_h2[(size_t)B_PAIRS * 256];              // 4 MB
static __device__ volatile int g_done1[32];
static __device__ volatile int g_done2[32];

// ---------------- init: zero counts + flags --------------------------------
__global__ void k_init() {
    int i = blockIdx.x * blockDim.x + threadIdx.x;
    if (i < N_NODES * R_REL) g_cnt[i] = 0;
    if (i < 32) { g_done1[i] = 0; g_done2[i] = 0; }
}

// ---------------- per-(dst,rel) edge counts ---------------------------------
__global__ void k_count(const int* __restrict__ ei, const int* __restrict__ et) {
    int e = blockIdx.x * blockDim.x + threadIdx.x;
    if (e >= E_EDGES) return;
    int dst = ei[E_EDGES + e];
    int r   = et[e];
    atomicAdd(&g_cnt[(size_t)dst * R_REL + r], 1);
}

// ---------------- effective relation weights: W_eff[l][i][o192] -------------
// o192 = r*32+o for r<5 (basis-combined); r==5 slot holds root[l].
__global__ void k_weff(const float* __restrict__ basis,
                       const float* __restrict__ comp,
                       const float* __restrict__ root) {
    int idx = blockIdx.x * blockDim.x + threadIdx.x;
    if (idx >= L_LAYERS * 32 * 192) return;
    int l = idx / (32 * 192);
    int rem = idx % (32 * 192);
    int i = rem / 192;
    int o = rem % 192;
    int r = o / 32, j = o % 32;
    float v;
    if (r < R_REL) {
        v = 0.f;
        #pragma unroll
        for (int b = 0; b < 4; b++)
            v += comp[(l * R_REL + r) * 4 + b] * basis[(((size_t)l * 4 + b) * 32 + i) * 32 + j];
    } else {
        v = root[((size_t)l * 32 + i) * 32 + j];
    }
    g_weff[idx] = v;
}

// ---------------- node transform: relfeat + (root@h + bias) -> g_agg --------
// block = 192 threads (one per output column), 32 nodes per block.
__global__ void k_transform(const float* __restrict__ x,
                            const float* __restrict__ cbias, int l) {
    __shared__ __align__(16) float hs[32][32];
    int n0 = blockIdx.x * 32;
    int tid = threadIdx.x;  // 0..191

    // load h tile (coalesced)
    for (int i = tid; i < 1024; i += 192) {
        int m = i >> 5, c = i & 31;
        float v;
        if (l == 0) v = x[(size_t)(n0 + m) * 32 + c];
        else        v = g_states[(size_t)(n0 + m) * 128 + (l - 1) * 32 + c];
        hs[m][c] = v;
    }
    // weights for this column into registers
    float wreg[32];
    const float* W = g_weff + l * 32 * 192;
    #pragma unroll
    for (int i = 0; i < 32; i++) wreg[i] = W[i * 192 + tid];
    __syncthreads();

    int r = tid / 32, o = tid % 32;
    float bias = (r == 5) ? cbias[o] : 0.f;

    for (int m = 0; m < 32; m++) {
        const float4* hp = (const float4*)hs[m];
        float acc = 0.f;
        #pragma unroll
        for (int i4 = 0; i4 < 8; i4++) {
            float4 h4 = hp[i4];
            acc += h4.x * wreg[i4 * 4 + 0];
            acc += h4.y * wreg[i4 * 4 + 1];
            acc += h4.z * wreg[i4 * 4 + 2];
            acc += h4.w * wreg[i4 * 4 + 3];
        }
        if (r < R_REL)
            g_relfeat[((size_t)(n0 + m) * R_REL + r) * 32 + o] = acc;
        else
            g_agg[(size_t)(n0 + m) * 32 + o] = acc + bias;
    }
}

// ---------------- edge aggregation: warp per edge, lane per feature ---------
__global__ void k_edge(const int* __restrict__ ei, const int* __restrict__ et) {
    int gid = blockIdx.x * blockDim.x + threadIdx.x;
    int e = gid >> 5;
    int lane = gid & 31;
    if (e >= E_EDGES) return;
    int src = ei[e];
    int dst = ei[E_EDGES + e];
    int r   = et[e];
    int cnt = g_cnt[(size_t)dst * R_REL + r];
    float norm = 1.0f / (float)(cnt < 1 ? 1 : cnt);
    float v = g_relfeat[((size_t)src * R_REL + r) * 32 + lane] * norm;
    atomicAdd(&g_agg[(size_t)dst * 32 + lane], v);
}

// ---------------- tanh + write into concat states ---------------------------
__global__ void k_tanh(int l) {
    int i = blockIdx.x * blockDim.x + threadIdx.x;
    if (i >= N_NODES * 32) return;
    int n = i >> 5, o = i & 31;
    g_states[(size_t)n * 128 + l * 32 + o] = tanhf(g_agg[i]);
}

// ---------------- gather z = [states[user], states[item]] -------------------
__global__ void k_gather(const int* __restrict__ ui, const int* __restrict__ vi) {
    int i = blockIdx.x * blockDim.x + threadIdx.x;
    if (i >= B_PAIRS * 256) return;
    int b = i >> 8, o = i & 255;
    int node = (o < 128) ? ui[b] : vi[b];
    g_z[i] = g_states[(size_t)node * 128 + (o & 127)];
}

// ---------------- persistent 2-layer LSTM scan ------------------------------
// 64 CTAs x 1024 threads. Blocks 0..31 = layer 0, 32..63 = layer 1.
// CTA k owns h-indices j in [8k, 8k+8). warp w: gate part p=w>>3, jj=w&7.
// lane covers 8 weight columns. Cross-CTA sync: per-CTA monotonic step flags.
__global__ void __launch_bounds__(1024, 1)
k_scan(const float* __restrict__ w_ih, const float* __restrict__ w_hh,
       const float* __restrict__ b_ih, const float* __restrict__ b_hh) {
    int blk = blockIdx.x;
    int layer = blk >> 5;
    int k = blk & 31;
    int tid = threadIdx.x;
    int w = tid >> 5, lane = tid & 31;
    int p = w >> 3, jj = w & 7;
    int j = k * 8 + jj;
    int row = p * 256 + j;

    const float* Wih = w_ih + (size_t)layer * 1024 * 256 + (size_t)row * 256 + lane * 8;
    const float* Whh = w_hh + (size_t)layer * 1024 * 256 + (size_t)row * 256 + lane * 8;
    float wih[8], whh[8];
    #pragma unroll
    for (int c = 0; c < 8; c++) { wih[c] = Wih[c]; whh[c] = Whh[c]; }
    float bias = b_ih[layer * 1024 + row] + b_hh[layer * 1024 + row];

    const float* inp  = (layer == 0) ? g_z  : g_h1;
    float*       hout = (layer == 0) ? g_h1 : g_h2;
    volatile int* own_done = (layer == 0) ? g_done1 : g_done2;

    __shared__ float gates_s[32];
    float cstate = 0.f;  // live only on warp 0, lanes 0..7

    for (int t = 0; t < T_STEPS; t++) {
        // ---- wait for producers ----
        if (w == 0) {
            if (layer == 0) {
                if (t > 0) { while (g_done1[lane] < t) { } }
            } else {
                while (g_done1[lane] < t + 1) { }
                if (t > 0) { while (g_done2[lane] < t) { } }
            }
            __threadfence();
        }
        __syncthreads();

        // ---- gather inputs ----
        const float4* xp = (const float4*)(inp + (size_t)t * 256 + lane * 8);
        float4 xa = xp[0], xb = xp[1];
        float4 ha, hb;
        if (t > 0) {
            const float4* hp = (const float4*)(hout + (size_t)(t - 1) * 256 + lane * 8);
            ha = hp[0]; hb = hp[1];
        } else {
            ha = make_float4(0.f, 0.f, 0.f, 0.f);
            hb = ha;
        }

        float acc = 0.f;
        acc += wih[0] * xa.x + wih[1] * xa.y + wih[2] * xa.z + wih[3] * xa.w;
        acc += wih[4] * xb.x + wih[5] * xb.y + wih[6] * xb.z + wih[7] * xb.w;
        acc += whh[0] * ha.x + whh[1] * ha.y + whh[2] * ha.z + whh[3] * ha.w;
        acc += whh[4] * hb.x + whh[5] * hb.y + whh[6] * hb.z + whh[7] * hb.w;
        #pragma unroll
        for (int s = 16; s > 0; s >>= 1)
            acc += __shfl_xor_sync(0xffffffffu, acc, s);
        if (lane == 0) gates_s[w] = acc + bias;
        __syncthreads();

        // ---- cell update: warp 0 lanes 0..7 ----
        if (w == 0 && lane < 8) {
            float ig = 1.f / (1.f + expf(-gates_s[lane]));
            float fg = 1.f / (1.f + expf(-gates_s[8 + lane]));
            float gg = tanhf(gates_s[16 + lane]);
            float og = 1.f / (1.f + expf(-gates_s[24 + lane]));
            cstate = fg * cstate + ig * gg;
            float h = og * tanhf(cstate);
            hout[(size_t)t * 256 + k * 8 + lane] = h;
        }
        __syncthreads();

        // ---- publish ----
        if (tid == 0) {
            __threadfence();
            own_done[k] = t + 1;
        }
    }
}

// ---------------- final MLP head ---------------------------------------------
__global__ void k_head(const float* __restrict__ l1w, const float* __restrict__ l1b,
                       const float* __restrict__ l2w, const float* __restrict__ l2b,
                       float* __restrict__ out) {
    int b = blockIdx.x;
    int tid = threadIdx.x;  // 256 threads
    int w = tid >> 5, lane = tid & 31;
    __shared__ float hs[256];
    __shared__ float rs[128];
    __shared__ float part[8];

    hs[tid] = g_h2[(size_t)b * 256 + tid];
    __syncthreads();

    // lin1: 8 warps x 16 rows each
    for (int q = 0; q < 16; q++) {
        int jrow = w * 16 + q;
        const float4* wp = (const float4*)(l1w + (size_t)jrow * 256 + lane * 8);
        float4 wa = wp[0], wb = wp[1];
        const float4* hp = (const float4*)(hs + lane * 8);
        float4 haa = hp[0], hbb = hp[1];
        float acc = wa.x * haa.x + wa.y * haa.y + wa.z * haa.z + wa.w * haa.w
                  + wb.x * hbb.x + wb.y * hbb.y + wb.z * hbb.z + wb.w * hbb.w;
        #pragma unroll
        for (int s = 16; s > 0; s >>= 1)
            acc += __shfl_xor_sync(0xffffffffu, acc, s);
        if (lane == 0) rs[jrow] = fmaxf(acc + l1b[jrow], 0.f);
    }
    __syncthreads();

    // lin2: 128-dot
    float v = (tid < 128) ? rs[tid] * l2w[tid] : 0.f;
    #pragma unroll
    for (int s = 16; s > 0; s >>= 1)
        v += __shfl_xor_sync(0xffffffffu, v, s);
    if (lane == 0) part[w] = v;
    __syncthreads();
    if (tid == 0) {
        float s = 0.f;
        #pragma unroll
        for (int i = 0; i < 8; i++) s += part[i];
        out[b] = s + l2b[0];
    }
}

// ---------------- launch -----------------------------------------------------
extern "C" void kernel_launch(void* const* d_in, const int* in_sizes, int n_in,
                              void* d_out, int out_size) {
    const float* x     = (const float*)d_in[0];
    const int*   ei    = (const int*)  d_in[1];
    const int*   et    = (const int*)  d_in[2];
    const int*   ui    = (const int*)  d_in[3];
    const int*   vi    = (const int*)  d_in[4];
    const float* basis = (const float*)d_in[5];
    const float* comp  = (const float*)d_in[6];
    const float* root  = (const float*)d_in[7];
    const float* cbias = (const float*)d_in[8];
    const float* w_ih  = (const float*)d_in[9];
    const float* w_hh  = (const float*)d_in[10];
    const float* b_ih  = (const float*)d_in[11];
    const float* b_hh  = (const float*)d_in[12];
    const float* l1w   = (const float*)d_in[13];
    const float* l1b   = (const float*)d_in[14];
    const float* l2w   = (const float*)d_in[15];
    const float* l2b   = (const float*)d_in[16];
    float* out = (float*)d_out;

    k_init<<<(N_NODES * R_REL + 255) / 256, 256>>>();
    k_count<<<(E_EDGES + 255) / 256, 256>>>(ei, et);
    k_weff<<<(L_LAYERS * 32 * 192 + 255) / 256, 256>>>(basis, comp, root);

    for (int l = 0; l < L_LAYERS; l++) {
        k_transform<<<N_NODES / 32, 192>>>(x, cbias + l * 32, l);
        k_edge<<<(E_EDGES * 32) / 256, 256>>>(ei, et);
        k_tanh<<<(N_NODES * 32) / 256, 256>>>(l);
    }

    k_gather<<<(B_PAIRS * 256) / 256, 256>>>(ui, vi);
    k_scan<<<64, 1024>>>(w_ih, w_hh, b_ih, b_hh);
    k_head<<<B_PAIRS, 256>>>(l1w, l1b, l2w, l2b, out);
}

// round 4
// speedup vs baseline: 1.6239x; 1.6239x over previous
#include <cuda_runtime.h>
#include <math.h>
#include <stdint.h>
#include <stddef.h>

#define N_NODES 131072
#define E_EDGES 2097152
#define B_PAIRS 4096
#define R_REL   5
#define L_LAYERS 4
#define T_STEPS 4096

// ---------------- device scratch (static globals; no runtime allocation) ----
static __device__ float g_relfeat[(size_t)N_NODES * R_REL * 32];  // 80 MB
static __device__ float g_agg[(size_t)N_NODES * 32];              // 16 MB
static __device__ float g_states[(size_t)N_NODES * 128];          // 64 MB
static __device__ int   g_cnt[(size_t)N_NODES * R_REL];           // 2.5 MB
static __device__ float g_weff[L_LAYERS * 32 * 192];              // 96 KB
static __device__ float g_z [(size_t)B_PAIRS * 256];              // 4 MB
static __device__ float g_xg[(size_t)T_STEPS * 1024];             // 16 MB
static __device__ unsigned long long g_h1p[(size_t)T_STEPS * 256];  // 8 MB packed (h, tag)
static __device__ unsigned long long g_h2p[(size_t)T_STEPS * 256];  // 8 MB packed (h, tag)

// ---------------- packed publish/poll: scalar b64, release/acquire ----------
// Single 8-byte naturally aligned STRONG access => single-copy atomic, plus
// acquire/release ordering. (v2.u32 vectors are only per-element atomic!)
__device__ __forceinline__ float poll_word(const unsigned long long* p, unsigned tag) {
    unsigned long long w;
    do {
        asm volatile("ld.global.acquire.gpu.b64 %0, [%1];"
                     : "=l"(w) : "l"(p) : "memory");
    } while ((unsigned)(w >> 32) != tag);
    return __uint_as_float((unsigned)(w & 0xffffffffull));
}
__device__ __forceinline__ void publish_word(unsigned long long* p, float h, unsigned tag) {
    unsigned long long w = ((unsigned long long)tag << 32)
                         | (unsigned long long)__float_as_uint(h);
    asm volatile("st.global.release.gpu.b64 [%0], %1;"
                 :: "l"(p), "l"(w) : "memory");
}

// ---------------- init: zero counts ------------------------------------------
__global__ void k_init() {
    int i = blockIdx.x * blockDim.x + threadIdx.x;
    if (i < N_NODES * R_REL) g_cnt[i] = 0;
}

// ---------------- zero the packed tag buffers (graph-replay safe) ------------
__global__ void k_zerotags() {
    size_t i = (size_t)blockIdx.x * blockDim.x + threadIdx.x;
    if (i < (size_t)T_STEPS * 256) {
        g_h1p[i] = 0ull;
        g_h2p[i] = 0ull;
    }
}

// ---------------- per-(dst,rel) edge counts ----------------------------------
__global__ void k_count(const int* __restrict__ ei, const int* __restrict__ et) {
    int e = blockIdx.x * blockDim.x + threadIdx.x;
    if (e >= E_EDGES) return;
    int dst = ei[E_EDGES + e];
    int r   = et[e];
    atomicAdd(&g_cnt[(size_t)dst * R_REL + r], 1);
}

// ---------------- effective relation weights ---------------------------------
__global__ void k_weff(const float* __restrict__ basis,
                       const float* __restrict__ comp,
                       const float* __restrict__ root) {
    int idx = blockIdx.x * blockDim.x + threadIdx.x;
    if (idx >= L_LAYERS * 32 * 192) return;
    int l = idx / (32 * 192);
    int rem = idx % (32 * 192);
    int i = rem / 192;
    int o = rem % 192;
    int r = o / 32, j = o % 32;
    float v;
    if (r < R_REL) {
        v = 0.f;
        #pragma unroll
        for (int b = 0; b < 4; b++)
            v += comp[(l * R_REL + r) * 4 + b] * basis[(((size_t)l * 4 + b) * 32 + i) * 32 + j];
    } else {
        v = root[((size_t)l * 32 + i) * 32 + j];
    }
    g_weff[idx] = v;
}

// ---------------- node transform ---------------------------------------------
__global__ void k_transform(const float* __restrict__ x,
                            const float* __restrict__ cbias, int l) {
    __shared__ __align__(16) float hs[32][32];
    int n0 = blockIdx.x * 32;
    int tid = threadIdx.x;  // 0..191

    for (int i = tid; i < 1024; i += 192) {
        int m = i >> 5, c = i & 31;
        float v;
        if (l == 0) v = x[(size_t)(n0 + m) * 32 + c];
        else        v = g_states[(size_t)(n0 + m) * 128 + (l - 1) * 32 + c];
        hs[m][c] = v;
    }
    float wreg[32];
    const float* W = g_weff + l * 32 * 192;
    #pragma unroll
    for (int i = 0; i < 32; i++) wreg[i] = W[i * 192 + tid];
    __syncthreads();

    int r = tid / 32, o = tid % 32;
    float bias = (r == 5) ? cbias[o] : 0.f;

    for (int m = 0; m < 32; m++) {
        const float4* hp = (const float4*)hs[m];
        float acc = 0.f;
        #pragma unroll
        for (int i4 = 0; i4 < 8; i4++) {
            float4 h4 = hp[i4];
            acc += h4.x * wreg[i4 * 4 + 0];
            acc += h4.y * wreg[i4 * 4 + 1];
            acc += h4.z * wreg[i4 * 4 + 2];
            acc += h4.w * wreg[i4 * 4 + 3];
        }
        if (r < R_REL)
            g_relfeat[((size_t)(n0 + m) * R_REL + r) * 32 + o] = acc;
        else
            g_agg[(size_t)(n0 + m) * 32 + o] = acc + bias;
    }
}

// ---------------- edge aggregation -------------------------------------------
__global__ void k_edge(const int* __restrict__ ei, const int* __restrict__ et) {
    int gid = blockIdx.x * blockDim.x + threadIdx.x;
    int e = gid >> 5;
    int lane = gid & 31;
    if (e >= E_EDGES) return;
    int src = ei[e];
    int dst = ei[E_EDGES + e];
    int r   = et[e];
    int cnt = g_cnt[(size_t)dst * R_REL + r];
    float norm = 1.0f / (float)(cnt < 1 ? 1 : cnt);
    float v = g_relfeat[((size_t)src * R_REL + r) * 32 + lane] * norm;
    atomicAdd(&g_agg[(size_t)dst * 32 + lane], v);
}

// ---------------- tanh into concat states ------------------------------------
__global__ void k_tanh(int l) {
    int i = blockIdx.x * blockDim.x + threadIdx.x;
    if (i >= N_NODES * 32) return;
    int n = i >> 5, o = i & 31;
    g_states[(size_t)n * 128 + l * 32 + o] = tanhf(g_agg[i]);
}

// ---------------- gather z = [states[user], states[item]] --------------------
__global__ void k_gather(const int* __restrict__ ui, const int* __restrict__ vi) {
    int i = blockIdx.x * blockDim.x + threadIdx.x;
    if (i >= B_PAIRS * 256) return;
    int b = i >> 8, o = i & 255;
    int node = (o < 128) ? ui[b] : vi[b];
    g_z[i] = g_states[(size_t)node * 128 + (o & 127)];
}

// ---------------- x-gates GEMM for layer 0: g_xg = g_z @ W_ih0^T + biases -----
__global__ void __launch_bounds__(256)
k_xg(const float* __restrict__ wih, const float* __restrict__ bih,
     const float* __restrict__ bhh) {
    __shared__ __align__(16) float As[32][65];
    __shared__ __align__(16) float Bs[32][65];
    int tid = threadIdx.x;
    int m0 = blockIdx.y * 64, n0 = blockIdx.x * 64;
    int tm = tid >> 4, tn = tid & 15;
    float acc[4][4];
    #pragma unroll
    for (int u = 0; u < 4; u++)
        #pragma unroll
        for (int v = 0; v < 4; v++) acc[u][v] = 0.f;

    for (int k0 = 0; k0 < 256; k0 += 32) {
        for (int i = tid; i < 512; i += 256) {
            int mm = i >> 3, kq = i & 7;
            float4 v = *(const float4*)&g_z[(size_t)(m0 + mm) * 256 + k0 + kq * 4];
            As[kq * 4 + 0][mm] = v.x; As[kq * 4 + 1][mm] = v.y;
            As[kq * 4 + 2][mm] = v.z; As[kq * 4 + 3][mm] = v.w;
        }
        for (int i = tid; i < 512; i += 256) {
            int nn = i >> 3, kq = i & 7;
            float4 v = *(const float4*)&wih[(size_t)(n0 + nn) * 256 + k0 + kq * 4];
            Bs[kq * 4 + 0][nn] = v.x; Bs[kq * 4 + 1][nn] = v.y;
            Bs[kq * 4 + 2][nn] = v.z; Bs[kq * 4 + 3][nn] = v.w;
        }
        __syncthreads();
        #pragma unroll
        for (int kk = 0; kk < 32; kk++) {
            float a[4], b[4];
            #pragma unroll
            for (int u = 0; u < 4; u++) { a[u] = As[kk][tm * 4 + u]; b[u] = Bs[kk][tn * 4 + u]; }
            #pragma unroll
            for (int u = 0; u < 4; u++)
                #pragma unroll
                for (int v = 0; v < 4; v++) acc[u][v] += a[u] * b[v];
        }
        __syncthreads();
    }
    #pragma unroll
    for (int u = 0; u < 4; u++)
        #pragma unroll
        for (int v = 0; v < 4; v++) {
            int rr = n0 + tn * 4 + v;
            g_xg[(size_t)(m0 + tm * 4 + u) * 1024 + rr] = acc[u][v] + bih[rr] + bhh[rr];
        }
}

// ---------------- persistent 2-layer LSTM scan -------------------------------
// 32 CTAs x 512 threads. Blocks 0..15 = layer 0, 16..31 = layer 1.
// CTA k owns h-indices [16k,16k+16). Warp w -> h-index j=16k+w.
// Lane = p*8+s: p=gate (i,f,g,o), s=column slice (32 cols each).
__global__ void __launch_bounds__(512, 1)
k_scan(const float* __restrict__ wih_g, const float* __restrict__ whh_g,
       const float* __restrict__ bih, const float* __restrict__ bhh) {
    int blk = blockIdx.x;
    int layer = blk >> 4;
    int k = blk & 15;
    int tid = threadIdx.x;
    int w = tid >> 5, lane = tid & 31;
    int p = lane >> 3, s = lane & 7;
    int j = k * 16 + w;          // h index 0..255
    int row = p * 256 + j;       // gate row 0..1023

    float wih[32], whh[32];
    {
        const float* WhhP = whh_g + (size_t)layer * 1024 * 256 + (size_t)row * 256 + s * 32;
        #pragma unroll
        for (int c = 0; c < 32; c++) whh[c] = WhhP[c];
    }
    if (layer == 1) {
        const float* WihP = wih_g + (size_t)1024 * 256 + (size_t)row * 256 + s * 32;
        #pragma unroll
        for (int c = 0; c < 32; c++) wih[c] = WihP[c];
    } else {
        #pragma unroll
        for (int c = 0; c < 32; c++) wih[c] = 0.f;
    }
    float bias = 0.f;
    if (layer == 1 && s == 0) bias = bih[1024 + row] + bhh[1024 + row];

    unsigned long long* outp = (layer == 0) ? g_h1p : g_h2p;

    __shared__ __align__(16) float hA[2][288];
    __shared__ __align__(16) float hB[2][288];

    float cst = 0.f;  // cell state, live on lane 0 of each warp

    #pragma unroll 1
    for (int t = 0; t < T_STEPS; t++) {
        int buf = t & 1;
        float xg = 0.f;
        if (layer == 0 && s == 0)
            xg = __ldg(&g_xg[(size_t)t * 1024 + row]);

        // ---- poll phase: fill smem with required h vectors ----
        if (layer == 0) {
            if (t > 0 && tid < 256) {
                float v = poll_word(&g_h1p[(size_t)(t - 1) * 256 + tid], (unsigned)t);
                hA[buf][(tid >> 5) * 36 + (tid & 31)] = v;
            }
        } else {
            if (tid < 256) {
                float v = poll_word(&g_h1p[(size_t)t * 256 + tid], (unsigned)(t + 1));
                hA[buf][(tid >> 5) * 36 + (tid & 31)] = v;
            } else if (t > 0) {
                int c = tid - 256;
                float v = poll_word(&g_h2p[(size_t)(t - 1) * 256 + c], (unsigned)t);
                hB[buf][(c >> 5) * 36 + (c & 31)] = v;
            }
        }
        __syncthreads();

        // ---- gate dot products ----
        float acc = 0.f;
        if (layer == 0) {
            if (t > 0) {
                const float4* hp = (const float4*)&hA[buf][s * 36];
                #pragma unroll
                for (int q = 0; q < 8; q++) {
                    float4 h4 = hp[q];
                    acc += whh[4*q] * h4.x + whh[4*q+1] * h4.y
                         + whh[4*q+2] * h4.z + whh[4*q+3] * h4.w;
                }
            }
        } else {
            const float4* xp = (const float4*)&hA[buf][s * 36];
            #pragma unroll
            for (int q = 0; q < 8; q++) {
                float4 h4 = xp[q];
                acc += wih[4*q] * h4.x + wih[4*q+1] * h4.y
                     + wih[4*q+2] * h4.z + wih[4*q+3] * h4.w;
            }
            if (t > 0) {
                const float4* hp = (const float4*)&hB[buf][s * 36];
                #pragma unroll
                for (int q = 0; q < 8; q++) {
                    float4 h4 = hp[q];
                    acc += whh[4*q] * h4.x + whh[4*q+1] * h4.y
                         + whh[4*q+2] * h4.z + whh[4*q+3] * h4.w;
                }
            }
        }
        acc += __shfl_xor_sync(0xffffffffu, acc, 4);
        acc += __shfl_xor_sync(0xffffffffu, acc, 2);
        acc += __shfl_xor_sync(0xffffffffu, acc, 1);

        float gact = 0.f;
        if (s == 0) {
            float gv = acc + bias + xg;
            gact = (p == 2) ? tanhf(gv) : 1.f / (1.f + expf(-gv));
        }
        float gi = __shfl_sync(0xffffffffu, gact, 0);
        float gf = __shfl_sync(0xffffffffu, gact, 8);
        float gg = __shfl_sync(0xffffffffu, gact, 16);
        float go = __shfl_sync(0xffffffffu, gact, 24);

        if (lane == 0) {
            cst = gf * cst + gi * gg;
            float h = go * tanhf(cst);
            publish_word(&outp[(size_t)t * 256 + j], h, (unsigned)(t + 1));
        }
    }
}

// ---------------- final MLP head ----------------------------------------------
__global__ void k_head(const float* __restrict__ l1w, const float* __restrict__ l1b,
                       const float* __restrict__ l2w, const float* __restrict__ l2b,
                       float* __restrict__ out) {
    int b = blockIdx.x;
    int tid = threadIdx.x;  // 256 threads
    int w = tid >> 5, lane = tid & 31;
    __shared__ __align__(16) float hs[256];
    __shared__ float rs[128];
    __shared__ float part[8];

    hs[tid] = __uint_as_float((unsigned)(g_h2p[(size_t)b * 256 + tid] & 0xffffffffull));
    __syncthreads();

    for (int q = 0; q < 16; q++) {
        int jrow = w * 16 + q;
        const float4* wp = (const float4*)(l1w + (size_t)jrow * 256 + lane * 8);
        float4 wa = wp[0], wb = wp[1];
        const float4* hp = (const float4*)(hs + lane * 8);
        float4 haa = hp[0], hbb = hp[1];
        float acc = wa.x * haa.x + wa.y * haa.y + wa.z * haa.z + wa.w * haa.w
                  + wb.x * hbb.x + wb.y * hbb.y + wb.z * hbb.z + wb.w * hbb.w;
        #pragma unroll
        for (int sft = 16; sft > 0; sft >>= 1)
            acc += __shfl_xor_sync(0xffffffffu, acc, sft);
        if (lane == 0) rs[jrow] = fmaxf(acc + l1b[jrow], 0.f);
    }
    __syncthreads();

    float v = (tid < 128) ? rs[tid] * l2w[tid] : 0.f;
    #pragma unroll
    for (int sft = 16; sft > 0; sft >>= 1)
        v += __shfl_xor_sync(0xffffffffu, v, sft);
    if (lane == 0) part[w] = v;
    __syncthreads();
    if (tid == 0) {
        float sum = 0.f;
        #pragma unroll
        for (int i = 0; i < 8; i++) sum += part[i];
        out[b] = sum + l2b[0];
    }
}

// ---------------- launch --------------------------------------------------------
extern "C" void kernel_launch(void* const* d_in, const int* in_sizes, int n_in,
                              void* d_out, int out_size) {
    const float* x     = (const float*)d_in[0];
    const int*   ei    = (const int*)  d_in[1];
    const int*   et    = (const int*)  d_in[2];
    const int*   ui    = (const int*)  d_in[3];
    const int*   vi    = (const int*)  d_in[4];
    const float* basis = (const float*)d_in[5];
    const float* comp  = (const float*)d_in[6];
    const float* root  = (const float*)d_in[7];
    const float* cbias = (const float*)d_in[8];
    const float* w_ih  = (const float*)d_in[9];
    const float* w_hh  = (const float*)d_in[10];
    const float* b_ih  = (const float*)d_in[11];
    const float* b_hh  = (const float*)d_in[12];
    const float* l1w   = (const float*)d_in[13];
    const float* l1b   = (const float*)d_in[14];
    const float* l2w   = (const float*)d_in[15];
    const float* l2b   = (const float*)d_in[16];
    float* out = (float*)d_out;

    k_init<<<(N_NODES * R_REL + 255) / 256, 256>>>();
    k_zerotags<<<(T_STEPS * 256 + 255) / 256, 256>>>();
    k_count<<<(E_EDGES + 255) / 256, 256>>>(ei, et);
    k_weff<<<(L_LAYERS * 32 * 192 + 255) / 256, 256>>>(basis, comp, root);

    for (int l = 0; l < L_LAYERS; l++) {
        k_transform<<<N_NODES / 32, 192>>>(x, cbias + l * 32, l);
        k_edge<<<(E_EDGES * 32) / 256, 256>>>(ei, et);
        k_tanh<<<(N_NODES * 32) / 256, 256>>>(l);
    }

    k_gather<<<(B_PAIRS * 256) / 256, 256>>>(ui, vi);
    k_xg<<<dim3(16, 64), 256>>>(w_ih, b_ih, b_hh);
    k_scan<<<32, 512>>>(w_ih, w_hh, b_ih, b_hh);
    k_head<<<B_PAIRS, 256>>>(l1w, l1b, l2w, l2b, out);
}

// round 5
// speedup vs baseline: 1.7933x; 1.1043x over previous
#include <cuda_runtime.h>
#include <math.h>
#include <stdint.h>
#include <stddef.h>

#define N_NODES 131072
#define E_EDGES 2097152
#define B_PAIRS 4096
#define R_REL   5
#define L_LAYERS 4
#define T_STEPS 4096

// ---------------- device scratch (static globals; no runtime allocation) ----
static __device__ float g_relfeat[(size_t)N_NODES * R_REL * 32];  // 80 MB
static __device__ float g_agg[(size_t)N_NODES * 32];              // 16 MB
static __device__ float g_states[(size_t)N_NODES * 128];          // 64 MB
static __device__ int   g_cnt[(size_t)N_NODES * R_REL];           // 2.5 MB
static __device__ float g_weff[L_LAYERS * 32 * 192];              // 96 KB
static __device__ float g_z [(size_t)B_PAIRS * 256];              // 4 MB
static __device__ float g_xg[(size_t)T_STEPS * 1024];             // 16 MB
static __device__ unsigned long long g_h1p[(size_t)T_STEPS * 256];  // packed (h, tag)
static __device__ unsigned long long g_h2p[(size_t)T_STEPS * 256];  // packed (h, tag)

// ---------------- packed publish/poll: scalar b64, release/acquire ----------
__device__ __forceinline__ float poll_word(const unsigned long long* p, unsigned tag) {
    unsigned long long w;
    do {
        asm volatile("ld.global.acquire.gpu.b64 %0, [%1];"
                     : "=l"(w) : "l"(p) : "memory");
    } while ((unsigned)(w >> 32) != tag);
    return __uint_as_float((unsigned)(w & 0xffffffffull));
}
__device__ __forceinline__ void publish_word(unsigned long long* p, float h, unsigned tag) {
    unsigned long long w = ((unsigned long long)tag << 32)
                         | (unsigned long long)__float_as_uint(h);
    asm volatile("st.global.release.gpu.b64 [%0], %1;"
                 :: "l"(p), "l"(w) : "memory");
}

// ---------------- cluster / mbarrier helpers --------------------------------
__device__ __forceinline__ uint32_t smem_u32(const void* p) {
    uint32_t a;
    asm("{ .reg .u64 t; cvta.to.shared.u64 t, %1; cvt.u32.u64 %0, t; }"
        : "=r"(a) : "l"(p));
    return a;
}
__device__ __forceinline__ void mbar_init(uint32_t addr, uint32_t cnt) {
    asm volatile("mbarrier.init.shared.b64 [%0], %1;" :: "r"(addr), "r"(cnt) : "memory");
}
__device__ __forceinline__ void mbar_wait_cluster(uint32_t addr, int phase) {
    asm volatile(
        "{\n\t"
        ".reg .pred P;\n\t"
        "WAITL_%=:\n\t"
        "mbarrier.try_wait.parity.acquire.cluster.shared::cta.b64 P, [%0], %1, 0x989680;\n\t"
        "@P bra.uni WDONE_%=;\n\t"
        "bra.uni WAITL_%=;\n\t"
        "WDONE_%=:\n\t"
        "}"
        :: "r"(addr), "r"(phase) : "memory");
}
__device__ __forceinline__ uint32_t mapa_u32(uint32_t addr, uint32_t rank) {
    uint32_t r;
    asm("mapa.shared::cluster.u32 %0, %1, %2;" : "=r"(r) : "r"(addr), "r"(rank));
    return r;
}
__device__ __forceinline__ void dsmem_st(uint32_t addr, float v) {
    asm volatile("st.shared::cluster.f32 [%0], %1;" :: "r"(addr), "f"(v) : "memory");
}
__device__ __forceinline__ void mbar_arrive_cluster(uint32_t addr) {
    asm volatile("mbarrier.arrive.shared::cluster.b64 _, [%0];" :: "r"(addr) : "memory");
}
__device__ __forceinline__ void cluster_sync_() {
    asm volatile("barrier.cluster.arrive.aligned;" ::: "memory");
    asm volatile("barrier.cluster.wait.aligned;" ::: "memory");
}

// ---------------- init: zero counts ------------------------------------------
__global__ void k_init() {
    int i = blockIdx.x * blockDim.x + threadIdx.x;
    if (i < N_NODES * R_REL) g_cnt[i] = 0;
}

// ---------------- zero the packed tag buffers (graph-replay safe) ------------
__global__ void k_zerotags() {
    size_t i = (size_t)blockIdx.x * blockDim.x + threadIdx.x;
    if (i < (size_t)T_STEPS * 256) {
        g_h1p[i] = 0ull;
        g_h2p[i] = 0ull;
    }
}

// ---------------- per-(dst,rel) edge counts ----------------------------------
__global__ void k_count(const int* __restrict__ ei, const int* __restrict__ et) {
    int e = blockIdx.x * blockDim.x + threadIdx.x;
    if (e >= E_EDGES) return;
    int dst = ei[E_EDGES + e];
    int r   = et[e];
    atomicAdd(&g_cnt[(size_t)dst * R_REL + r], 1);
}

// ---------------- effective relation weights ---------------------------------
__global__ void k_weff(const float* __restrict__ basis,
                       const float* __restrict__ comp,
                       const float* __restrict__ root) {
    int idx = blockIdx.x * blockDim.x + threadIdx.x;
    if (idx >= L_LAYERS * 32 * 192) return;
    int l = idx / (32 * 192);
    int rem = idx % (32 * 192);
    int i = rem / 192;
    int o = rem % 192;
    int r = o / 32, j = o % 32;
    float v;
    if (r < R_REL) {
        v = 0.f;
        #pragma unroll
        for (int b = 0; b < 4; b++)
            v += comp[(l * R_REL + r) * 4 + b] * basis[(((size_t)l * 4 + b) * 32 + i) * 32 + j];
    } else {
        v = root[((size_t)l * 32 + i) * 32 + j];
    }
    g_weff[idx] = v;
}

// ---------------- node transform ---------------------------------------------
__global__ void k_transform(const float* __restrict__ x,
                            const float* __restrict__ cbias, int l) {
    __shared__ __align__(16) float hs[32][32];
    int n0 = blockIdx.x * 32;
    int tid = threadIdx.x;  // 0..191

    for (int i = tid; i < 1024; i += 192) {
        int m = i >> 5, c = i & 31;
        float v;
        if (l == 0) v = x[(size_t)(n0 + m) * 32 + c];
        else        v = g_states[(size_t)(n0 + m) * 128 + (l - 1) * 32 + c];
        hs[m][c] = v;
    }
    float wreg[32];
    const float* W = g_weff + l * 32 * 192;
    #pragma unroll
    for (int i = 0; i < 32; i++) wreg[i] = W[i * 192 + tid];
    __syncthreads();

    int r = tid / 32, o = tid % 32;
    float bias = (r == 5) ? cbias[o] : 0.f;

    for (int m = 0; m < 32; m++) {
        const float4* hp = (const float4*)hs[m];
        float acc = 0.f;
        #pragma unroll
        for (int i4 = 0; i4 < 8; i4++) {
            float4 h4 = hp[i4];
            acc += h4.x * wreg[i4 * 4 + 0];
            acc += h4.y * wreg[i4 * 4 + 1];
            acc += h4.z * wreg[i4 * 4 + 2];
            acc += h4.w * wreg[i4 * 4 + 3];
        }
        if (r < R_REL)
            g_relfeat[((size_t)(n0 + m) * R_REL + r) * 32 + o] = acc;
        else
            g_agg[(size_t)(n0 + m) * 32 + o] = acc + bias;
    }
}

// ---------------- edge aggregation -------------------------------------------
__global__ void k_edge(const int* __restrict__ ei, const int* __restrict__ et) {
    int gid = blockIdx.x * blockDim.x + threadIdx.x;
    int e = gid >> 5;
    int lane = gid & 31;
    if (e >= E_EDGES) return;
    int src = ei[e];
    int dst = ei[E_EDGES + e];
    int r   = et[e];
    int cnt = g_cnt[(size_t)dst * R_REL + r];
    float norm = 1.0f / (float)(cnt < 1 ? 1 : cnt);
    float v = g_relfeat[((size_t)src * R_REL + r) * 32 + lane] * norm;
    atomicAdd(&g_agg[(size_t)dst * 32 + lane], v);
}

// ---------------- tanh into concat states ------------------------------------
__global__ void k_tanh(int l) {
    int i = blockIdx.x * blockDim.x + threadIdx.x;
    if (i >= N_NODES * 32) return;
    int n = i >> 5, o = i & 31;
    g_states[(size_t)n * 128 + l * 32 + o] = tanhf(g_agg[i]);
}

// ---------------- gather z = [states[user], states[item]] --------------------
__global__ void k_gather(const int* __restrict__ ui, const int* __restrict__ vi) {
    int i = blockIdx.x * blockDim.x + threadIdx.x;
    if (i >= B_PAIRS * 256) return;
    int b = i >> 8, o = i & 255;
    int node = (o < 128) ? ui[b] : vi[b];
    g_z[i] = g_states[(size_t)node * 128 + (o & 127)];
}

// ---------------- x-gates GEMM for layer 0 ------------------------------------
__global__ void __launch_bounds__(256)
k_xg(const float* __restrict__ wih, const float* __restrict__ bih,
     const float* __restrict__ bhh) {
    __shared__ __align__(16) float As[32][65];
    __shared__ __align__(16) float Bs[32][65];
    int tid = threadIdx.x;
    int m0 = blockIdx.y * 64, n0 = blockIdx.x * 64;
    int tm = tid >> 4, tn = tid & 15;
    float acc[4][4];
    #pragma unroll
    for (int u = 0; u < 4; u++)
        #pragma unroll
        for (int v = 0; v < 4; v++) acc[u][v] = 0.f;

    for (int k0 = 0; k0 < 256; k0 += 32) {
        for (int i = tid; i < 512; i += 256) {
            int mm = i >> 3, kq = i & 7;
            float4 v = *(const float4*)&g_z[(size_t)(m0 + mm) * 256 + k0 + kq * 4];
            As[kq * 4 + 0][mm] = v.x; As[kq * 4 + 1][mm] = v.y;
            As[kq * 4 + 2][mm] = v.z; As[kq * 4 + 3][mm] = v.w;
        }
        for (int i = tid; i < 512; i += 256) {
            int nn = i >> 3, kq = i & 7;
            float4 v = *(const float4*)&wih[(size_t)(n0 + nn) * 256 + k0 + kq * 4];
            Bs[kq * 4 + 0][nn] = v.x; Bs[kq * 4 + 1][nn] = v.y;
            Bs[kq * 4 + 2][nn] = v.z; Bs[kq * 4 + 3][nn] = v.w;
        }
        __syncthreads();
        #pragma unroll
        for (int kk = 0; kk < 32; kk++) {
            float a[4], b[4];
            #pragma unroll
            for (int u = 0; u < 4; u++) { a[u] = As[kk][tm * 4 + u]; b[u] = Bs[kk][tn * 4 + u]; }
            #pragma unroll
            for (int u = 0; u < 4; u++)
                #pragma unroll
                for (int v = 0; v < 4; v++) acc[u][v] += a[u] * b[v];
        }
        __syncthreads();
    }
    #pragma unroll
    for (int u = 0; u < 4; u++)
        #pragma unroll
        for (int v = 0; v < 4; v++) {
            int rr = n0 + tn * 4 + v;
            g_xg[(size_t)(m0 + tm * 4 + u) * 1024 + rr] = acc[u][v] + bih[rr] + bhh[rr];
        }
}

// ---------------- cluster LSTM scan -------------------------------------------
// 32 CTAs x 512 threads, cluster=(16,1,1): cluster 0 = layer 0, cluster 1 = layer 1.
// Within a layer: CTA rank k owns h-indices [16k,16k+16); warp w -> j=16k+w.
// Lane = p*8+s: gate p, 32-col slice s. Intra-layer h exchange via DSMEM +
// remote mbarrier arrivals (2 buffers, 256 arrivals each, provably race-free).
// Layer0 -> layer1 handoff stays on L2 tag-words (pipeline lag, not in loop).
__global__ void __launch_bounds__(512, 1)
k_scan_cluster(const float* __restrict__ wih_g, const float* __restrict__ whh_g,
               const float* __restrict__ bih, const float* __restrict__ bhh) {
    int layer = blockIdx.x >> 4;
    uint32_t crank;
    asm("mov.u32 %0, %%cluster_ctarank;" : "=r"(crank));
    int tid = threadIdx.x;
    int w = tid >> 5, lane = tid & 31;
    int p = lane >> 3, s = lane & 7;
    int j = (int)crank * 16 + w;   // h index 0..255
    int row = p * 256 + j;         // gate row 0..1023

    float whh[32], wih[32];
    {
        const float* WhhP = whh_g + (size_t)layer * 262144 + (size_t)row * 256 + s * 32;
        #pragma unroll
        for (int c = 0; c < 32; c++) whh[c] = WhhP[c];
    }
    if (layer == 1) {
        const float* WihP = wih_g + (size_t)262144 + (size_t)row * 256 + s * 32;
        #pragma unroll
        for (int c = 0; c < 32; c++) wih[c] = WihP[c];
    } else {
        #pragma unroll
        for (int c = 0; c < 32; c++) wih[c] = 0.f;
    }
    float bias = 0.f;
    if (layer == 1 && s == 0) bias = bih[1024 + row] + bhh[1024 + row];

    __shared__ __align__(16) float hA[2][288];   // own-layer h(t-1), DSMEM-filled
    __shared__ __align__(16) float hX[2][288];   // layer1: h1(t) from L2
    __shared__ __align__(8) unsigned long long barA[2];

    uint32_t bar0 = smem_u32(&barA[0]);
    uint32_t bar1 = smem_u32(&barA[1]);
    if (tid == 0) { mbar_init(bar0, 256); mbar_init(bar1, 256); }
    __syncthreads();
    cluster_sync_();   // all bars init'd before any remote arrival

    // per-lane remote targets (lanes 0..15 publish to peer CTA = lane)
    int slot = (j >> 5) * 36 + (j & 31);
    uint32_t peer = (uint32_t)(lane & 15);
    uint32_t rA0 = mapa_u32(smem_u32(&hA[0][slot]), peer);
    uint32_t rA1 = mapa_u32(smem_u32(&hA[1][slot]), peer);
    uint32_t rB0 = mapa_u32(bar0, peer);
    uint32_t rB1 = mapa_u32(bar1, peer);

    int ph0 = 0, ph1 = 0;
    float cst = 0.f;

    #pragma unroll 1
    for (int t = 0; t < T_STEPS; t++) {
        int buf = t & 1;
        float xg = 0.f;
        if (layer == 0 && s == 0)
            xg = __ldg(&g_xg[(size_t)t * 1024 + row]);

        // layer1: poll h1(t) from L2 into hX[buf]
        if (layer == 1 && tid < 256) {
            float v = poll_word(&g_h1p[(size_t)t * 256 + tid], (unsigned)(t + 1));
            hX[buf][(tid >> 5) * 36 + (tid & 31)] = v;
        }
        // wait own-layer h(t-1) arrivals
        int pb = (t - 1) & 1;
        if (t > 0) {
            if (pb == 0) { mbar_wait_cluster(bar0, ph0); ph0 ^= 1; }
            else         { mbar_wait_cluster(bar1, ph1); ph1 ^= 1; }
        }
        if (layer == 1) __syncthreads();   // hX visibility across warps

        // gate dot products
        float acc = 0.f;
        if (layer == 0) {
            if (t > 0) {
                const float4* hp = (const float4*)&hA[pb][s * 36];
                #pragma unroll
                for (int q = 0; q < 8; q++) {
                    float4 h4 = hp[q];
                    acc += whh[4*q] * h4.x + whh[4*q+1] * h4.y
                         + whh[4*q+2] * h4.z + whh[4*q+3] * h4.w;
                }
            }
        } else {
            const float4* xp = (const float4*)&hX[buf][s * 36];
            #pragma unroll
            for (int q = 0; q < 8; q++) {
                float4 h4 = xp[q];
                acc += wih[4*q] * h4.x + wih[4*q+1] * h4.y
                     + wih[4*q+2] * h4.z + wih[4*q+3] * h4.w;
            }
            if (t > 0) {
                const float4* hp = (const float4*)&hA[pb][s * 36];
                #pragma unroll
                for (int q = 0; q < 8; q++) {
                    float4 h4 = hp[q];
                    acc += whh[4*q] * h4.x + whh[4*q+1] * h4.y
                         + whh[4*q+2] * h4.z + whh[4*q+3] * h4.w;
                }
            }
        }
        acc += __shfl_xor_sync(0xffffffffu, acc, 4);
        acc += __shfl_xor_sync(0xffffffffu, acc, 2);
        acc += __shfl_xor_sync(0xffffffffu, acc, 1);

        float gact = 0.f;
        if (s == 0) {
            float gv = acc + bias + xg;
            gact = (p == 2) ? tanhf(gv) : __fdividef(1.f, 1.f + __expf(-gv));
        }
        float gi = __shfl_sync(0xffffffffu, gact, 0);
        float gf = __shfl_sync(0xffffffffu, gact, 8);
        float gg = __shfl_sync(0xffffffffu, gact, 16);
        float go = __shfl_sync(0xffffffffu, gact, 24);

        float h = 0.f;
        if (lane == 0) {
            cst = gf * cst + gi * gg;
            h = go * tanhf(cst);
        }
        h = __shfl_sync(0xffffffffu, h, 0);

        // publish: lanes 0..15 -> DSMEM peers; lane 16 -> L2 for next stage
        if (lane < 16) {
            dsmem_st(buf ? rA1 : rA0, h);
            mbar_arrive_cluster(buf ? rB1 : rB0);
        } else if (lane == 16) {
            unsigned long long wrd = ((unsigned long long)(unsigned)(t + 1) << 32)
                                   | (unsigned long long)__float_as_uint(h);
            if (layer == 0)
                asm volatile("st.global.release.gpu.b64 [%0], %1;"
                             :: "l"(&g_h1p[(size_t)t * 256 + j]), "l"(wrd) : "memory");
            else
                asm volatile("st.global.cg.b64 [%0], %1;"
                             :: "l"(&g_h2p[(size_t)t * 256 + j]), "l"(wrd) : "memory");
        }
    }
    cluster_sync_();   // no CTA exits while peers' DSMEM ops may be in flight
}

// ---------------- fallback L2-tag scan (round-3 proven) -----------------------
__global__ void __launch_bounds__(512, 1)
k_scan_l2(const float* __restrict__ wih_g, const float* __restrict__ whh_g,
          const float* __restrict__ bih, const float* __restrict__ bhh) {
    int blk = blockIdx.x;
    int layer = blk >> 4;
    int k = blk & 15;
    int tid = threadIdx.x;
    int w = tid >> 5, lane = tid & 31;
    int p = lane >> 3, s = lane & 7;
    int j = k * 16 + w;
    int row = p * 256 + j;

    float wih[32], whh[32];
    {
        const float* WhhP = whh_g + (size_t)layer * 262144 + (size_t)row * 256 + s * 32;
        #pragma unroll
        for (int c = 0; c < 32; c++) whh[c] = WhhP[c];
    }
    if (layer == 1) {
        const float* WihP = wih_g + (size_t)262144 + (size_t)row * 256 + s * 32;
        #pragma unroll
        for (int c = 0; c < 32; c++) wih[c] = WihP[c];
    } else {
        #pragma unroll
        for (int c = 0; c < 32; c++) wih[c] = 0.f;
    }
    float bias = 0.f;
    if (layer == 1 && s == 0) bias = bih[1024 + row] + bhh[1024 + row];

    unsigned long long* outp = (layer == 0) ? g_h1p : g_h2p;
    __shared__ __align__(16) float hA[2][288];
    __shared__ __align__(16) float hB[2][288];
    float cst = 0.f;

    #pragma unroll 1
    for (int t = 0; t < T_STEPS; t++) {
        int buf = t & 1;
        float xg = 0.f;
        if (layer == 0 && s == 0)
            xg = __ldg(&g_xg[(size_t)t * 1024 + row]);

        if (layer == 0) {
            if (t > 0 && tid < 256) {
                float v = poll_word(&g_h1p[(size_t)(t - 1) * 256 + tid], (unsigned)t);
                hA[buf][(tid >> 5) * 36 + (tid & 31)] = v;
            }
        } else {
            if (tid < 256) {
                float v = poll_word(&g_h1p[(size_t)t * 256 + tid], (unsigned)(t + 1));
                hA[buf][(tid >> 5) * 36 + (tid & 31)] = v;
            } else if (t > 0) {
                int c = tid - 256;
                float v = poll_word(&g_h2p[(size_t)(t - 1) * 256 + c], (unsigned)t);
                hB[buf][(c >> 5) * 36 + (c & 31)] = v;
            }
        }
        __syncthreads();

        float acc = 0.f;
        if (layer == 0) {
            if (t > 0) {
                const float4* hp = (const float4*)&hA[buf][s * 36];
                #pragma unroll
                for (int q = 0; q < 8; q++) {
                    float4 h4 = hp[q];
                    acc += whh[4*q] * h4.x + whh[4*q+1] * h4.y
                         + whh[4*q+2] * h4.z + whh[4*q+3] * h4.w;
                }
            }
        } else {
            const float4* xp = (const float4*)&hA[buf][s * 36];
            #pragma unroll
            for (int q = 0; q < 8; q++) {
                float4 h4 = xp[q];
                acc += wih[4*q] * h4.x + wih[4*q+1] * h4.y
                     + wih[4*q+2] * h4.z + wih[4*q+3] * h4.w;
            }
            if (t > 0) {
                const float4* hp = (const float4*)&hB[buf][s * 36];
                #pragma unroll
                for (int q = 0; q < 8; q++) {
                    float4 h4 = hp[q];
                    acc += whh[4*q] * h4.x + whh[4*q+1] * h4.y
                         + whh[4*q+2] * h4.z + whh[4*q+3] * h4.w;
                }
            }
        }
        acc += __shfl_xor_sync(0xffffffffu, acc, 4);
        acc += __shfl_xor_sync(0xffffffffu, acc, 2);
        acc += __shfl_xor_sync(0xffffffffu, acc, 1);

        float gact = 0.f;
        if (s == 0) {
            float gv = acc + bias + xg;
            gact = (p == 2) ? tanhf(gv) : __fdividef(1.f, 1.f + __expf(-gv));
        }
        float gi = __shfl_sync(0xffffffffu, gact, 0);
        float gf = __shfl_sync(0xffffffffu, gact, 8);
        float gg = __shfl_sync(0xffffffffu, gact, 16);
        float go = __shfl_sync(0xffffffffu, gact, 24);

        if (lane == 0) {
            cst = gf * cst + gi * gg;
            float h = go * tanhf(cst);
            publish_word(&outp[(size_t)t * 256 + j], h, (unsigned)(t + 1));
        }
    }
}

// ---------------- final MLP head ----------------------------------------------
__global__ void k_head(const float* __restrict__ l1w, const float* __restrict__ l1b,
                       const float* __restrict__ l2w, const float* __restrict__ l2b,
                       float* __restrict__ out) {
    int b = blockIdx.x;
    int tid = threadIdx.x;  // 256 threads
    int w = tid >> 5, lane = tid & 31;
    __shared__ __align__(16) float hs[256];
    __shared__ float rs[128];
    __shared__ float part[8];

    hs[tid] = __uint_as_float((unsigned)(g_h2p[(size_t)b * 256 + tid] & 0xffffffffull));
    __syncthreads();

    for (int q = 0; q < 16; q++) {
        int jrow = w * 16 + q;
        const float4* wp = (const float4*)(l1w + (size_t)jrow * 256 + lane * 8);
        float4 wa = wp[0], wb = wp[1];
        const float4* hp = (const float4*)(hs + lane * 8);
        float4 haa = hp[0], hbb = hp[1];
        float acc = wa.x * haa.x + wa.y * haa.y + wa.z * haa.z + wa.w * haa.w
                  + wb.x * hbb.x + wb.y * hbb.y + wb.z * hbb.z + wb.w * hbb.w;
        #pragma unroll
        for (int sft = 16; sft > 0; sft >>= 1)
            acc += __shfl_xor_sync(0xffffffffu, acc, sft);
        if (lane == 0) rs[jrow] = fmaxf(acc + l1b[jrow], 0.f);
    }
    __syncthreads();

    float v = (tid < 128) ? rs[tid] * l2w[tid] : 0.f;
    #pragma unroll
    for (int sft = 16; sft > 0; sft >>= 1)
        v += __shfl_xor_sync(0xffffffffu, v, sft);
    if (lane == 0) part[w] = v;
    __syncthreads();
    if (tid == 0) {
        float sum = 0.f;
        #pragma unroll
        for (int i = 0; i < 8; i++) sum += part[i];
        out[b] = sum + l2b[0];
    }
}

// ---------------- launch --------------------------------------------------------
extern "C" void kernel_launch(void* const* d_in, const int* in_sizes, int n_in,
                              void* d_out, int out_size) {
    const float* x     = (const float*)d_in[0];
    const int*   ei    = (const int*)  d_in[1];
    const int*   et    = (const int*)  d_in[2];
    const int*   ui    = (const int*)  d_in[3];
    const int*   vi    = (const int*)  d_in[4];
    const float* basis = (const float*)d_in[5];
    const float* comp  = (const float*)d_in[6];
    const float* root  = (const float*)d_in[7];
    const float* cbias = (const float*)d_in[8];
    const float* w_ih  = (const float*)d_in[9];
    const float* w_hh  = (const float*)d_in[10];
    const float* b_ih  = (const float*)d_in[11];
    const float* b_hh  = (const float*)d_in[12];
    const float* l1w   = (const float*)d_in[13];
    const float* l1b   = (const float*)d_in[14];
    const float* l2w   = (const float*)d_in[15];
    const float* l2b   = (const float*)d_in[16];
    float* out = (float*)d_out;

    k_init<<<(N_NODES * R_REL + 255) / 256, 256>>>();
    k_zerotags<<<(T_STEPS * 256 + 255) / 256, 256>>>();
    k_count<<<(E_EDGES + 255) / 256, 256>>>(ei, et);
    k_weff<<<(L_LAYERS * 32 * 192 + 255) / 256, 256>>>(basis, comp, root);

    for (int l = 0; l < L_LAYERS; l++) {
        k_transform<<<N_NODES / 32, 192>>>(x, cbias + l * 32, l);
        k_edge<<<(E_EDGES * 32) / 256, 256>>>(ei, et);
        k_tanh<<<(N_NODES * 32) / 256, 256>>>(l);
    }

    k_gather<<<(B_PAIRS * 256) / 256, 256>>>(ui, vi);
    k_xg<<<dim3(16, 64), 256>>>(w_ih, b_ih, b_hh);

    // cluster scan (16-CTA non-portable clusters); fallback to L2-tag scan
    cudaError_t arc = cudaFuncSetAttribute(
        k_scan_cluster, cudaFuncAttributeNonPortableClusterSizeAllowed, 1);
    if (arc == cudaSuccess) {
        cudaLaunchConfig_t cfg = {};
        cfg.gridDim = dim3(32, 1, 1);
        cfg.blockDim = dim3(512, 1, 1);
        cfg.dynamicSmemBytes = 0;
        cudaLaunchAttribute attrs[1];
        attrs[0].id = cudaLaunchAttributeClusterDimension;
        attrs[0].val.clusterDim.x = 16;
        attrs[0].val.clusterDim.y = 1;
        attrs[0].val.clusterDim.z = 1;
        cfg.attrs = attrs;
        cfg.numAttrs = 1;
        cudaError_t lrc = cudaLaunchKernelEx(&cfg, k_scan_cluster, w_ih, w_hh, b_ih, b_hh);
        if (lrc != cudaSuccess)
            k_scan_l2<<<32, 512>>>(w_ih, w_hh, b_ih, b_hh);
    } else {
        k_scan_l2<<<32, 512>>>(w_ih, w_hh, b_ih, b_hh);
    }

    k_head<<<B_PAIRS, 256>>>(l1w, l1b, l2w, l2b, out);
}

// round 6
// speedup vs baseline: 1.9328x; 1.0778x over previous
#include <cuda_runtime.h>
#include <math.h>
#include <stdint.h>
#include <stddef.h>

#define N_NODES 131072
#define E_EDGES 2097152
#define B_PAIRS 4096
#define R_REL   5
#define L_LAYERS 4
#define T_STEPS 4096

// ---------------- device scratch (static globals; no runtime allocation) ----
static __device__ float g_relfeat[(size_t)N_NODES * R_REL * 32];  // 80 MB
static __device__ float g_agg[(size_t)N_NODES * 32];              // 16 MB
static __device__ float g_states[(size_t)N_NODES * 128];          // 64 MB
static __device__ int   g_cnt[(size_t)N_NODES * R_REL];           // 2.5 MB
static __device__ float g_weff[L_LAYERS * 32 * 192];              // 96 KB
static __device__ float g_z [(size_t)B_PAIRS * 256];              // 4 MB
static __device__ float g_xg[(size_t)T_STEPS * 1024];             // 16 MB
static __device__ unsigned long long g_h1p[(size_t)T_STEPS * 256];  // packed (h, tag)
static __device__ unsigned long long g_h2p[(size_t)T_STEPS * 256];  // packed (h, tag)

// ---------------- packed publish/poll: scalar b64, release/acquire ----------
__device__ __forceinline__ float poll_word(const unsigned long long* p, unsigned tag) {
    unsigned long long w;
    do {
        asm volatile("ld.global.acquire.gpu.b64 %0, [%1];"
                     : "=l"(w) : "l"(p) : "memory");
    } while ((unsigned)(w >> 32) != tag);
    return __uint_as_float((unsigned)(w & 0xffffffffull));
}
__device__ __forceinline__ void publish_word(unsigned long long* p, float h, unsigned tag) {
    unsigned long long w = ((unsigned long long)tag << 32)
                         | (unsigned long long)__float_as_uint(h);
    asm volatile("st.global.release.gpu.b64 [%0], %1;"
                 :: "l"(p), "l"(w) : "memory");
}

// ---------------- cluster / mbarrier helpers --------------------------------
__device__ __forceinline__ uint32_t smem_u32(const void* p) {
    uint32_t a;
    asm("{ .reg .u64 t; cvta.to.shared.u64 t, %1; cvt.u32.u64 %0, t; }"
        : "=r"(a) : "l"(p));
    return a;
}
__device__ __forceinline__ void mbar_init(uint32_t addr, uint32_t cnt) {
    asm volatile("mbarrier.init.shared.b64 [%0], %1;" :: "r"(addr), "r"(cnt) : "memory");
}
__device__ __forceinline__ void mbar_arrive_expect(uint32_t addr, uint32_t tx) {
    asm volatile("mbarrier.arrive.expect_tx.shared.b64 _, [%0], %1;"
                 :: "r"(addr), "r"(tx) : "memory");
}
__device__ __forceinline__ void mbar_wait_cluster(uint32_t addr, int phase) {
    asm volatile(
        "{\n\t"
        ".reg .pred P;\n\t"
        "WAITL_%=:\n\t"
        "mbarrier.try_wait.parity.acquire.cluster.shared::cta.b64 P, [%0], %1, 0x989680;\n\t"
        "@P bra.uni WDONE_%=;\n\t"
        "bra.uni WAITL_%=;\n\t"
        "WDONE_%=:\n\t"
        "}"
        :: "r"(addr), "r"(phase) : "memory");
}
__device__ __forceinline__ uint32_t mapa_u32(uint32_t addr, uint32_t rank) {
    uint32_t r;
    asm("mapa.shared::cluster.u32 %0, %1, %2;" : "=r"(r) : "r"(addr), "r"(rank));
    return r;
}
// data store that also completes tx-bytes on the TARGET CTA's mbarrier:
// one op delivers the value AND the synchronization — no arrive serialization.
__device__ __forceinline__ void st_async_f32(uint32_t daddr, float v, uint32_t mbar) {
    asm volatile("st.async.shared::cluster.mbarrier::complete_tx::bytes.b32 [%0], %1, [%2];"
                 :: "r"(daddr), "r"(__float_as_uint(v)), "r"(mbar) : "memory");
}
__device__ __forceinline__ void cluster_sync_() {
    asm volatile("barrier.cluster.arrive.aligned;" ::: "memory");
    asm volatile("barrier.cluster.wait.aligned;" ::: "memory");
}

// ---------------- init: zero counts ------------------------------------------
__global__ void k_init() {
    int i = blockIdx.x * blockDim.x + threadIdx.x;
    if (i < N_NODES * R_REL) g_cnt[i] = 0;
}

// ---------------- zero the packed tag buffers (graph-replay safe) ------------
__global__ void k_zerotags() {
    size_t i = (size_t)blockIdx.x * blockDim.x + threadIdx.x;
    if (i < (size_t)T_STEPS * 256) {
        g_h1p[i] = 0ull;
        g_h2p[i] = 0ull;
    }
}

// ---------------- per-(dst,rel) edge counts ----------------------------------
__global__ void k_count(const int* __restrict__ ei, const int* __restrict__ et) {
    int e = blockIdx.x * blockDim.x + threadIdx.x;
    if (e >= E_EDGES) return;
    int dst = ei[E_EDGES + e];
    int r   = et[e];
    atomicAdd(&g_cnt[(size_t)dst * R_REL + r], 1);
}

// ---------------- effective relation weights ---------------------------------
__global__ void k_weff(const float* __restrict__ basis,
                       const float* __restrict__ comp,
                       const float* __restrict__ root) {
    int idx = blockIdx.x * blockDim.x + threadIdx.x;
    if (idx >= L_LAYERS * 32 * 192) return;
    int l = idx / (32 * 192);
    int rem = idx % (32 * 192);
    int i = rem / 192;
    int o = rem % 192;
    int r = o / 32, j = o % 32;
    float v;
    if (r < R_REL) {
        v = 0.f;
        #pragma unroll
        for (int b = 0; b < 4; b++)
            v += comp[(l * R_REL + r) * 4 + b] * basis[(((size_t)l * 4 + b) * 32 + i) * 32 + j];
    } else {
        v = root[((size_t)l * 32 + i) * 32 + j];
    }
    g_weff[idx] = v;
}

// ---------------- node transform ---------------------------------------------
__global__ void k_transform(const float* __restrict__ x,
                            const float* __restrict__ cbias, int l) {
    __shared__ __align__(16) float hs[32][32];
    int n0 = blockIdx.x * 32;
    int tid = threadIdx.x;  // 0..191

    for (int i = tid; i < 1024; i += 192) {
        int m = i >> 5, c = i & 31;
        float v;
        if (l == 0) v = x[(size_t)(n0 + m) * 32 + c];
        else        v = g_states[(size_t)(n0 + m) * 128 + (l - 1) * 32 + c];
        hs[m][c] = v;
    }
    float wreg[32];
    const float* W = g_weff + l * 32 * 192;
    #pragma unroll
    for (int i = 0; i < 32; i++) wreg[i] = W[i * 192 + tid];
    __syncthreads();

    int r = tid / 32, o = tid % 32;
    float bias = (r == 5) ? cbias[o] : 0.f;

    for (int m = 0; m < 32; m++) {
        const float4* hp = (const float4*)hs[m];
        float acc = 0.f;
        #pragma unroll
        for (int i4 = 0; i4 < 8; i4++) {
            float4 h4 = hp[i4];
            acc += h4.x * wreg[i4 * 4 + 0];
            acc += h4.y * wreg[i4 * 4 + 1];
            acc += h4.z * wreg[i4 * 4 + 2];
            acc += h4.w * wreg[i4 * 4 + 3];
        }
        if (r < R_REL)
            g_relfeat[((size_t)(n0 + m) * R_REL + r) * 32 + o] = acc;
        else
            g_agg[(size_t)(n0 + m) * 32 + o] = acc + bias;
    }
}

// ---------------- edge aggregation -------------------------------------------
__global__ void k_edge(const int* __restrict__ ei, const int* __restrict__ et) {
    int gid = blockIdx.x * blockDim.x + threadIdx.x;
    int e = gid >> 5;
    int lane = gid & 31;
    if (e >= E_EDGES) return;
    int src = ei[e];
    int dst = ei[E_EDGES + e];
    int r   = et[e];
    int cnt = g_cnt[(size_t)dst * R_REL + r];
    float norm = 1.0f / (float)(cnt < 1 ? 1 : cnt);
    float v = g_relfeat[((size_t)src * R_REL + r) * 32 + lane] * norm;
    atomicAdd(&g_agg[(size_t)dst * 32 + lane], v);
}

// ---------------- tanh into concat states ------------------------------------
__global__ void k_tanh(int l) {
    int i = blockIdx.x * blockDim.x + threadIdx.x;
    if (i >= N_NODES * 32) return;
    int n = i >> 5, o = i & 31;
    g_states[(size_t)n * 128 + l * 32 + o] = tanhf(g_agg[i]);
}

// ---------------- gather z = [states[user], states[item]] --------------------
__global__ void k_gather(const int* __restrict__ ui, const int* __restrict__ vi) {
    int i = blockIdx.x * blockDim.x + threadIdx.x;
    if (i >= B_PAIRS * 256) return;
    int b = i >> 8, o = i & 255;
    int node = (o < 128) ? ui[b] : vi[b];
    g_z[i] = g_states[(size_t)node * 128 + (o & 127)];
}

// ---------------- x-gates GEMM for layer 0 ------------------------------------
__global__ void __launch_bounds__(256)
k_xg(const float* __restrict__ wih, const float* __restrict__ bih,
     const float* __restrict__ bhh) {
    __shared__ __align__(16) float As[32][65];
    __shared__ __align__(16) float Bs[32][65];
    int tid = threadIdx.x;
    int m0 = blockIdx.y * 64, n0 = blockIdx.x * 64;
    int tm = tid >> 4, tn = tid & 15;
    float acc[4][4];
    #pragma unroll
    for (int u = 0; u < 4; u++)
        #pragma unroll
        for (int v = 0; v < 4; v++) acc[u][v] = 0.f;

    for (int k0 = 0; k0 < 256; k0 += 32) {
        for (int i = tid; i < 512; i += 256) {
            int mm = i >> 3, kq = i & 7;
            float4 v = *(const float4*)&g_z[(size_t)(m0 + mm) * 256 + k0 + kq * 4];
            As[kq * 4 + 0][mm] = v.x; As[kq * 4 + 1][mm] = v.y;
            As[kq * 4 + 2][mm] = v.z; As[kq * 4 + 3][mm] = v.w;
        }
        for (int i = tid; i < 512; i += 256) {
            int nn = i >> 3, kq = i & 7;
            float4 v = *(const float4*)&wih[(size_t)(n0 + nn) * 256 + k0 + kq * 4];
            Bs[kq * 4 + 0][nn] = v.x; Bs[kq * 4 + 1][nn] = v.y;
            Bs[kq * 4 + 2][nn] = v.z; Bs[kq * 4 + 3][nn] = v.w;
        }
        __syncthreads();
        #pragma unroll
        for (int kk = 0; kk < 32; kk++) {
            float a[4], b[4];
            #pragma unroll
            for (int u = 0; u < 4; u++) { a[u] = As[kk][tm * 4 + u]; b[u] = Bs[kk][tn * 4 + u]; }
            #pragma unroll
            for (int u = 0; u < 4; u++)
                #pragma unroll
                for (int v = 0; v < 4; v++) acc[u][v] += a[u] * b[v];
        }
        __syncthreads();
    }
    #pragma unroll
    for (int u = 0; u < 4; u++)
        #pragma unroll
        for (int v = 0; v < 4; v++) {
            int rr = n0 + tn * 4 + v;
            g_xg[(size_t)(m0 + tm * 4 + u) * 1024 + rr] = acc[u][v] + bih[rr] + bhh[rr];
        }
}

// ---------------- cluster LSTM scan (st.async tx-bytes protocol) -------------
// 32 CTAs x 512 threads, cluster=(16,1,1): cluster 0 = layer 0, cluster 1 = layer 1.
// CTA rank k owns h-indices [16k,16k+16); warp w -> j=16k+w. Lane = p*8+s.
// h exchange: each warp's lanes 0..15 st.async its h to all 16 CTAs; the store
// itself completes 4 tx-bytes on the target's mbarrier (expect = 1024 B/step).
// No per-arrival atomics, no __syncthreads in layer 0's loop.
__global__ void __launch_bounds__(512, 1)
k_scan_cluster(const float* __restrict__ wih_g, const float* __restrict__ whh_g,
               const float* __restrict__ bih, const float* __restrict__ bhh) {
    int layer = blockIdx.x >> 4;
    uint32_t crank;
    asm("mov.u32 %0, %%cluster_ctarank;" : "=r"(crank));
    int tid = threadIdx.x;
    int w = tid >> 5, lane = tid & 31;
    int p = lane >> 3, s = lane & 7;
    int j = (int)crank * 16 + w;   // h index 0..255
    int row = p * 256 + j;         // gate row 0..1023

    float whh[32], wih[32];
    {
        const float* WhhP = whh_g + (size_t)layer * 262144 + (size_t)row * 256 + s * 32;
        #pragma unroll
        for (int c = 0; c < 32; c++) whh[c] = WhhP[c];
    }
    if (layer == 1) {
        const float* WihP = wih_g + (size_t)262144 + (size_t)row * 256 + s * 32;
        #pragma unroll
        for (int c = 0; c < 32; c++) wih[c] = WihP[c];
    } else {
        #pragma unroll
        for (int c = 0; c < 32; c++) wih[c] = 0.f;
    }
    float bias = 0.f;
    if (layer == 1 && s == 0) bias = bih[1024 + row] + bhh[1024 + row];

    __shared__ __align__(16) float hA[2][288];   // own-layer h, st.async-filled
    __shared__ __align__(16) float hX[2][288];   // layer1: h1(t) from L2
    __shared__ __align__(8) unsigned long long barA[2];

    uint32_t bar0 = smem_u32(&barA[0]);
    uint32_t bar1 = smem_u32(&barA[1]);
    if (tid == 0) { mbar_init(bar0, 1); mbar_init(bar1, 1); }
    __syncthreads();
    // pre-post expects for h(0) and h(1) phases, then cluster-sync so every
    // CTA's expect is visible before any peer can publish.
    if (tid == 0) { mbar_arrive_expect(bar0, 1024); mbar_arrive_expect(bar1, 1024); }
    cluster_sync_();

    // remote targets: lane k (k<16) publishes this warp's h to peer CTA k.
    int slot = (j >> 5) * 36 + (j & 31);
    uint32_t peer = (uint32_t)(lane & 15);
    uint32_t rA0 = mapa_u32(smem_u32(&hA[0][slot]), peer);
    uint32_t rA1 = mapa_u32(smem_u32(&hA[1][slot]), peer);
    uint32_t rM0 = mapa_u32(bar0, peer);
    uint32_t rM1 = mapa_u32(bar1, peer);

    int ph0 = 0, ph1 = 0;
    float cst = 0.f;

    #pragma unroll 1
    for (int t = 0; t < T_STEPS; t++) {
        int buf = t & 1;
        int pb = (t - 1) & 1;
        float xg = 0.f;
        if (layer == 0 && s == 0)
            xg = __ldg(&g_xg[(size_t)t * 1024 + row]);

        // layer1: poll h1(t) from L2 into hX[buf] (usually already present)
        if (layer == 1 && tid < 256) {
            float v = poll_word(&g_h1p[(size_t)t * 256 + tid], (unsigned)(t + 1));
            hX[buf][(tid >> 5) * 36 + (tid & 31)] = v;
        }
        // wait own-layer h(t-1); re-post expect for this mbar's next phase
        // (h(t+1)) immediately — provably before any peer can publish h(t+1).
        if (t > 0) {
            if (pb == 0) {
                mbar_wait_cluster(bar0, ph0); ph0 ^= 1;
                if (tid == 0) mbar_arrive_expect(bar0, 1024);
            } else {
                mbar_wait_cluster(bar1, ph1); ph1 ^= 1;
                if (tid == 0) mbar_arrive_expect(bar1, 1024);
            }
        }
        if (layer == 1) __syncthreads();   // hX visibility across warps

        // gate dot products
        float acc = 0.f;
        if (layer == 0) {
            if (t > 0) {
                const float4* hp = (const float4*)&hA[pb][s * 36];
                #pragma unroll
                for (int q = 0; q < 8; q++) {
                    float4 h4 = hp[q];
                    acc += whh[4*q] * h4.x + whh[4*q+1] * h4.y
                         + whh[4*q+2] * h4.z + whh[4*q+3] * h4.w;
                }
            }
        } else {
            const float4* xp = (const float4*)&hX[buf][s * 36];
            #pragma unroll
            for (int q = 0; q < 8; q++) {
                float4 h4 = xp[q];
                acc += wih[4*q] * h4.x + wih[4*q+1] * h4.y
                     + wih[4*q+2] * h4.z + wih[4*q+3] * h4.w;
            }
            if (t > 0) {
                const float4* hp = (const float4*)&hA[pb][s * 36];
                #pragma unroll
                for (int q = 0; q < 8; q++) {
                    float4 h4 = hp[q];
                    acc += whh[4*q] * h4.x + whh[4*q+1] * h4.y
                         + whh[4*q+2] * h4.z + whh[4*q+3] * h4.w;
                }
            }
        }
        acc += __shfl_xor_sync(0xffffffffu, acc, 4);
        acc += __shfl_xor_sync(0xffffffffu, acc, 2);
        acc += __shfl_xor_sync(0xffffffffu, acc, 1);

        float gact = 0.f;
        if (s == 0) {
            float gv = acc + bias + xg;
            gact = (p == 2) ? tanhf(gv) : __fdividef(1.f, 1.f + __expf(-gv));
        }
        float gi = __shfl_sync(0xffffffffu, gact, 0);
        float gf = __shfl_sync(0xffffffffu, gact, 8);
        float gg = __shfl_sync(0xffffffffu, gact, 16);
        float go = __shfl_sync(0xffffffffu, gact, 24);

        float h = 0.f;
        if (lane == 0) {
            cst = gf * cst + gi * gg;
            h = go * tanhf(cst);
        }
        h = __shfl_sync(0xffffffffu, h, 0);

        // publish: lanes 0..15 st.async to the 16 cluster CTAs (data+tx in one
        // op); lane 16 publishes to gmem for the next pipeline stage.
        if (lane < 16) {
            st_async_f32(buf ? rA1 : rA0, h, buf ? rM1 : rM0);
        } else if (lane == 16) {
            unsigned long long wrd = ((unsigned long long)(unsigned)(t + 1) << 32)
                                   | (unsigned long long)__float_as_uint(h);
            if (layer == 0)
                asm volatile("st.global.release.gpu.b64 [%0], %1;"
                             :: "l"(&g_h1p[(size_t)t * 256 + j]), "l"(wrd) : "memory");
            else
                asm volatile("st.global.cg.b64 [%0], %1;"
                             :: "l"(&g_h2p[(size_t)t * 256 + j]), "l"(wrd) : "memory");
        }
    }
    cluster_sync_();   // no CTA exits while peers' st.async may be in flight
}

// ---------------- fallback L2-tag scan (proven) --------------------------------
__global__ void __launch_bounds__(512, 1)
k_scan_l2(const float* __restrict__ wih_g, const float* __restrict__ whh_g,
          const float* __restrict__ bih, const float* __restrict__ bhh) {
    int blk = blockIdx.x;
    int layer = blk >> 4;
    int k = blk & 15;
    int tid = threadIdx.x;
    int w = tid >> 5, lane = tid & 31;
    int p = lane >> 3, s = lane & 7;
    int j = k * 16 + w;
    int row = p * 256 + j;

    float wih[32], whh[32];
    {
        const float* WhhP = whh_g + (size_t)layer * 262144 + (size_t)row * 256 + s * 32;
        #pragma unroll
        for (int c = 0; c < 32; c++) whh[c] = WhhP[c];
    }
    if (layer == 1) {
        const float* WihP = wih_g + (size_t)262144 + (size_t)row * 256 + s * 32;
        #pragma unroll
        for (int c = 0; c < 32; c++) wih[c] = WihP[c];
    } else {
        #pragma unroll
        for (int c = 0; c < 32; c++) wih[c] = 0.f;
    }
    float bias = 0.f;
    if (layer == 1 && s == 0) bias = bih[1024 + row] + bhh[1024 + row];

    unsigned long long* outp = (layer == 0) ? g_h1p : g_h2p;
    __shared__ __align__(16) float hA[2][288];
    __shared__ __align__(16) float hB[2][288];
    float cst = 0.f;

    #pragma unroll 1
    for (int t = 0; t < T_STEPS; t++) {
        int buf = t & 1;
        float xg = 0.f;
        if (layer == 0 && s == 0)
            xg = __ldg(&g_xg[(size_t)t * 1024 + row]);

        if (layer == 0) {
            if (t > 0 && tid < 256) {
                float v = poll_word(&g_h1p[(size_t)(t - 1) * 256 + tid], (unsigned)t);
                hA[buf][(tid >> 5) * 36 + (tid & 31)] = v;
            }
        } else {
            if (tid < 256) {
                float v = poll_word(&g_h1p[(size_t)t * 256 + tid], (unsigned)(t + 1));
                hA[buf][(tid >> 5) * 36 + (tid & 31)] = v;
            } else if (t > 0) {
                int c = tid - 256;
                float v = poll_word(&g_h2p[(size_t)(t - 1) * 256 + c], (unsigned)t);
                hB[buf][(c >> 5) * 36 + (c & 31)] = v;
            }
        }
        __syncthreads();

        float acc = 0.f;
        if (layer == 0) {
            if (t > 0) {
                const float4* hp = (const float4*)&hA[buf][s * 36];
                #pragma unroll
                for (int q = 0; q < 8; q++) {
                    float4 h4 = hp[q];
                    acc += whh[4*q] * h4.x + whh[4*q+1] * h4.y
                         + whh[4*q+2] * h4.z + whh[4*q+3] * h4.w;
                }
            }
        } else {
            const float4* xp = (const float4*)&hA[buf][s * 36];
            #pragma unroll
            for (int q = 0; q < 8; q++) {
                float4 h4 = xp[q];
                acc += wih[4*q] * h4.x + wih[4*q+1] * h4.y
                     + wih[4*q+2] * h4.z + wih[4*q+3] * h4.w;
            }
            if (t > 0) {
                const float4* hp = (const float4*)&hB[buf][s * 36];
                #pragma unroll
                for (int q = 0; q < 8; q++) {
                    float4 h4 = hp[q];
                    acc += whh[4*q] * h4.x + whh[4*q+1] * h4.y
                         + whh[4*q+2] * h4.z + whh[4*q+3] * h4.w;
                }
            }
        }
        acc += __shfl_xor_sync(0xffffffffu, acc, 4);
        acc += __shfl_xor_sync(0xffffffffu, acc, 2);
        acc += __shfl_xor_sync(0xffffffffu, acc, 1);

        float gact = 0.f;
        if (s == 0) {
            float gv = acc + bias + xg;
            gact = (p == 2) ? tanhf(gv) : __fdividef(1.f, 1.f + __expf(-gv));
        }
        float gi = __shfl_sync(0xffffffffu, gact, 0);
        float gf = __shfl_sync(0xffffffffu, gact, 8);
        float gg = __shfl_sync(0xffffffffu, gact, 16);
        float go = __shfl_sync(0xffffffffu, gact, 24);

        if (lane == 0) {
            cst = gf * cst + gi * gg;
            float h = go * tanhf(cst);
            publish_word(&outp[(size_t)t * 256 + j], h, (unsigned)(t + 1));
        }
    }
}

// ---------------- final MLP head ----------------------------------------------
__global__ void k_head(const float* __restrict__ l1w, const float* __restrict__ l1b,
                       const float* __restrict__ l2w, const float* __restrict__ l2b,
                       float* __restrict__ out) {
    int b = blockIdx.x;
    int tid = threadIdx.x;  // 256 threads
    int w = tid >> 5, lane = tid & 31;
    __shared__ __align__(16) float hs[256];
    __shared__ float rs[128];
    __shared__ float part[8];

    hs[tid] = __uint_as_float((unsigned)(g_h2p[(size_t)b * 256 + tid] & 0xffffffffull));
    __syncthreads();

    for (int q = 0; q < 16; q++) {
        int jrow = w * 16 + q;
        const float4* wp = (const float4*)(l1w + (size_t)jrow * 256 + lane * 8);
        float4 wa = wp[0], wb = wp[1];
        const float4* hp = (const float4*)(hs + lane * 8);
        float4 haa = hp[0], hbb = hp[1];
        float acc = wa.x * haa.x + wa.y * haa.y + wa.z * haa.z + wa.w * haa.w
                  + wb.x * hbb.x + wb.y * hbb.y + wb.z * hbb.z + wb.w * hbb.w;
        #pragma unroll
        for (int sft = 16; sft > 0; sft >>= 1)
            acc += __shfl_xor_sync(0xffffffffu, acc, sft);
        if (lane == 0) rs[jrow] = fmaxf(acc + l1b[jrow], 0.f);
    }
    __syncthreads();

    float v = (tid < 128) ? rs[tid] * l2w[tid] : 0.f;
    #pragma unroll
    for (int sft = 16; sft > 0; sft >>= 1)
        v += __shfl_xor_sync(0xffffffffu, v, sft);
    if (lane == 0) part[w] = v;
    __syncthreads();
    if (tid == 0) {
        float sum = 0.f;
        #pragma unroll
        for (int i = 0; i < 8; i++) sum += part[i];
        out[b] = sum + l2b[0];
    }
}

// ---------------- launch --------------------------------------------------------
extern "C" void kernel_launch(void* const* d_in, const int* in_sizes, int n_in,
                              void* d_out, int out_size) {
    const float* x     = (const float*)d_in[0];
    const int*   ei    = (const int*)  d_in[1];
    const int*   et    = (const int*)  d_in[2];
    const int*   ui    = (const int*)  d_in[3];
    const int*   vi    = (const int*)  d_in[4];
    const float* basis = (const float*)d_in[5];
    const float* comp  = (const float*)d_in[6];
    const float* root  = (const float*)d_in[7];
    const float* cbias = (const float*)d_in[8];
    const float* w_ih  = (const float*)d_in[9];
    const float* w_hh  = (const float*)d_in[10];
    const float* b_ih  = (const float*)d_in[11];
    const float* b_hh  = (const float*)d_in[12];
    const float* l1w   = (const float*)d_in[13];
    const float* l1b   = (const float*)d_in[14];
    const float* l2w   = (const float*)d_in[15];
    const float* l2b   = (const float*)d_in[16];
    float* out = (float*)d_out;

    k_init<<<(N_NODES * R_REL + 255) / 256, 256>>>();
    k_zerotags<<<(T_STEPS * 256 + 255) / 256, 256>>>();
    k_count<<<(E_EDGES + 255) / 256, 256>>>(ei, et);
    k_weff<<<(L_LAYERS * 32 * 192 + 255) / 256, 256>>>(basis, comp, root);

    for (int l = 0; l < L_LAYERS; l++) {
        k_transform<<<N_NODES / 32, 192>>>(x, cbias + l * 32, l);
        k_edge<<<(E_EDGES * 32) / 256, 256>>>(ei, et);
        k_tanh<<<(N_NODES * 32) / 256, 256>>>(l);
    }

    k_gather<<<(B_PAIRS * 256) / 256, 256>>>(ui, vi);
    k_xg<<<dim3(16, 64), 256>>>(w_ih, b_ih, b_hh);

    // cluster scan (16-CTA non-portable clusters) with occupancy pre-check;
    // fallback to proven L2-tag scan.
    bool launched = false;
    cudaError_t arc = cudaFuncSetAttribute(
        k_scan_cluster, cudaFuncAttributeNonPortableClusterSizeAllowed, 1);
    if (arc == cudaSuccess) {
        cudaLaunchConfig_t cfg = {};
        cfg.gridDim = dim3(32, 1, 1);
        cfg.blockDim = dim3(512, 1, 1);
        cfg.dynamicSmemBytes = 0;
        cudaLaunchAttribute attrs[1];
        attrs[0].id = cudaLaunchAttributeClusterDimension;
        attrs[0].val.clusterDim.x = 16;
        attrs[0].val.clusterDim.y = 1;
        attrs[0].val.clusterDim.z = 1;
        cfg.attrs = attrs;
        cfg.numAttrs = 1;
        int nclus = 0;
        cudaError_t qrc = cudaOccupancyMaxActiveClusters(&nclus, k_scan_cluster, &cfg);
        if (qrc == cudaSuccess && nclus >= 2) {
            if (cudaLaunchKernelEx(&cfg, k_scan_cluster, w_ih, w_hh, b_ih, b_hh)
                == cudaSuccess)
                launched = true;
        }
    }
    if (!launched)
        k_scan_l2<<<32, 512>>>(w_ih, w_hh, b_ih, b_hh);

    k_head<<<B_PAIRS, 256>>>(l1w, l1b, l2w, l2b, out);
}

// round 7
// speedup vs baseline: 2.0913x; 1.0820x over previous
#include <cuda_runtime.h>
#include <math.h>
#include <stdint.h>
#include <stddef.h>

#define N_NODES 131072
#define E_EDGES 2097152
#define B_PAIRS 4096
#define R_REL   5
#define L_LAYERS 4
#define T_STEPS 4096

// ---------------- device scratch (static globals; no runtime allocation) ----
static __device__ float g_relfeat[(size_t)N_NODES * R_REL * 32];  // 80 MB
static __device__ float g_agg[(size_t)N_NODES * 32];              // 16 MB
static __device__ float g_states[(size_t)N_NODES * 128];          // 64 MB
static __device__ int   g_cnt[(size_t)N_NODES * R_REL];           // 2.5 MB
static __device__ float g_weff[L_LAYERS * 32 * 192];              // 96 KB
static __device__ float g_z [(size_t)B_PAIRS * 256];              // 4 MB
static __device__ float g_xg[(size_t)T_STEPS * 1024];             // 16 MB
static __device__ unsigned long long g_h1p[(size_t)T_STEPS * 256];  // packed (h, tag)
static __device__ unsigned long long g_h2p[(size_t)T_STEPS * 256];  // packed (h, tag)

// ---------------- packed publish/poll: scalar b64, release/acquire ----------
__device__ __forceinline__ float poll_word(const unsigned long long* p, unsigned tag) {
    unsigned long long w;
    do {
        asm volatile("ld.global.acquire.gpu.b64 %0, [%1];"
                     : "=l"(w) : "l"(p) : "memory");
    } while ((unsigned)(w >> 32) != tag);
    return __uint_as_float((unsigned)(w & 0xffffffffull));
}
__device__ __forceinline__ void publish_word(unsigned long long* p, float h, unsigned tag) {
    unsigned long long w = ((unsigned long long)tag << 32)
                         | (unsigned long long)__float_as_uint(h);
    asm volatile("st.global.release.gpu.b64 [%0], %1;"
                 :: "l"(p), "l"(w) : "memory");
}

// ---------------- cluster / mbarrier helpers --------------------------------
__device__ __forceinline__ uint32_t smem_u32(const void* p) {
    uint32_t a;
    asm("{ .reg .u64 t; cvta.to.shared.u64 t, %1; cvt.u32.u64 %0, t; }"
        : "=r"(a) : "l"(p));
    return a;
}
__device__ __forceinline__ void mbar_init(uint32_t addr, uint32_t cnt) {
    asm volatile("mbarrier.init.shared.b64 [%0], %1;" :: "r"(addr), "r"(cnt) : "memory");
}
__device__ __forceinline__ void mbar_arrive_expect(uint32_t addr, uint32_t tx) {
    asm volatile("mbarrier.arrive.expect_tx.shared.b64 _, [%0], %1;"
                 :: "r"(addr), "r"(tx) : "memory");
}
__device__ __forceinline__ void mbar_wait_cluster(uint32_t addr, int phase) {
    asm volatile(
        "{\n\t"
        ".reg .pred P;\n\t"
        "WAITL_%=:\n\t"
        "mbarrier.try_wait.parity.acquire.cluster.shared::cta.b64 P, [%0], %1, 0x989680;\n\t"
        "@P bra.uni WDONE_%=;\n\t"
        "bra.uni WAITL_%=;\n\t"
        "WDONE_%=:\n\t"
        "}"
        :: "r"(addr), "r"(phase) : "memory");
}
__device__ __forceinline__ uint32_t mapa_u32(uint32_t addr, uint32_t rank) {
    uint32_t r;
    asm("mapa.shared::cluster.u32 %0, %1, %2;" : "=r"(r) : "r"(addr), "r"(rank));
    return r;
}
// 64-byte DSMEM bulk copy; the copy itself completes tx-bytes on the TARGET
// CTA's mbarrier. 16 of these replace 256 scalar st.async messages.
__device__ __forceinline__ void dsmem_bulk64(uint32_t dst, uint32_t src, uint32_t mbar) {
    asm volatile(
        "cp.async.bulk.shared::cluster.shared::cta.mbarrier::complete_tx::bytes "
        "[%0], [%1], 64, [%2];"
        :: "r"(dst), "r"(src), "r"(mbar) : "memory");
}
__device__ __forceinline__ void fence_proxy_async_cta() {
    asm volatile("fence.proxy.async.shared::cta;" ::: "memory");
}
__device__ __forceinline__ void cluster_sync_() {
    asm volatile("barrier.cluster.arrive.aligned;" ::: "memory");
    asm volatile("barrier.cluster.wait.aligned;" ::: "memory");
}

// ---------------- init: zero counts ------------------------------------------
__global__ void k_init() {
    int i = blockIdx.x * blockDim.x + threadIdx.x;
    if (i < N_NODES * R_REL) g_cnt[i] = 0;
}

// ---------------- zero the packed tag buffers (graph-replay safe) ------------
__global__ void k_zerotags() {
    size_t i = (size_t)blockIdx.x * blockDim.x + threadIdx.x;
    if (i < (size_t)T_STEPS * 256) {
        g_h1p[i] = 0ull;
        g_h2p[i] = 0ull;
    }
}

// ---------------- per-(dst,rel) edge counts ----------------------------------
__global__ void k_count(const int* __restrict__ ei, const int* __restrict__ et) {
    int e = blockIdx.x * blockDim.x + threadIdx.x;
    if (e >= E_EDGES) return;
    int dst = ei[E_EDGES + e];
    int r   = et[e];
    atomicAdd(&g_cnt[(size_t)dst * R_REL + r], 1);
}

// ---------------- effective relation weights ---------------------------------
__global__ void k_weff(const float* __restrict__ basis,
                       const float* __restrict__ comp,
                       const float* __restrict__ root) {
    int idx = blockIdx.x * blockDim.x + threadIdx.x;
    if (idx >= L_LAYERS * 32 * 192) return;
    int l = idx / (32 * 192);
    int rem = idx % (32 * 192);
    int i = rem / 192;
    int o = rem % 192;
    int r = o / 32, j = o % 32;
    float v;
    if (r < R_REL) {
        v = 0.f;
        #pragma unroll
        for (int b = 0; b < 4; b++)
            v += comp[(l * R_REL + r) * 4 + b] * basis[(((size_t)l * 4 + b) * 32 + i) * 32 + j];
    } else {
        v = root[((size_t)l * 32 + i) * 32 + j];
    }
    g_weff[idx] = v;
}

// ---------------- node transform ---------------------------------------------
__global__ void k_transform(const float* __restrict__ x,
                            const float* __restrict__ cbias, int l) {
    __shared__ __align__(16) float hs[32][32];
    int n0 = blockIdx.x * 32;
    int tid = threadIdx.x;  // 0..191

    for (int i = tid; i < 1024; i += 192) {
        int m = i >> 5, c = i & 31;
        float v;
        if (l == 0) v = x[(size_t)(n0 + m) * 32 + c];
        else        v = g_states[(size_t)(n0 + m) * 128 + (l - 1) * 32 + c];
        hs[m][c] = v;
    }
    float wreg[32];
    const float* W = g_weff + l * 32 * 192;
    #pragma unroll
    for (int i = 0; i < 32; i++) wreg[i] = W[i * 192 + tid];
    __syncthreads();

    int r = tid / 32, o = tid % 32;
    float bias = (r == 5) ? cbias[o] : 0.f;

    for (int m = 0; m < 32; m++) {
        const float4* hp = (const float4*)hs[m];
        float acc = 0.f;
        #pragma unroll
        for (int i4 = 0; i4 < 8; i4++) {
            float4 h4 = hp[i4];
            acc += h4.x * wreg[i4 * 4 + 0];
            acc += h4.y * wreg[i4 * 4 + 1];
            acc += h4.z * wreg[i4 * 4 + 2];
            acc += h4.w * wreg[i4 * 4 + 3];
        }
        if (r < R_REL)
            g_relfeat[((size_t)(n0 + m) * R_REL + r) * 32 + o] = acc;
        else
            g_agg[(size_t)(n0 + m) * 32 + o] = acc + bias;
    }
}

// ---------------- edge aggregation: 8 lanes/edge, vector reductions ----------
__global__ void k_edge(const int* __restrict__ ei, const int* __restrict__ et) {
    int gid = blockIdx.x * blockDim.x + threadIdx.x;
    int e = gid >> 3;
    int q = gid & 7;
    if (e >= E_EDGES) return;
    int src = ei[e];
    int dst = ei[E_EDGES + e];
    int r   = et[e];
    int cnt = g_cnt[(size_t)dst * R_REL + r];
    float norm = 1.0f / (float)(cnt < 1 ? 1 : cnt);
    float4 v = *(const float4*)&g_relfeat[((size_t)src * R_REL + r) * 32 + q * 4];
    float* p = &g_agg[(size_t)dst * 32 + q * 4];
    asm volatile("red.global.add.v4.f32 [%0], {%1,%2,%3,%4};"
                 :: "l"(p), "f"(v.x * norm), "f"(v.y * norm),
                    "f"(v.z * norm), "f"(v.w * norm)
                 : "memory");
}

// ---------------- tanh into concat states ------------------------------------
__global__ void k_tanh(int l) {
    int i = blockIdx.x * blockDim.x + threadIdx.x;
    if (i >= N_NODES * 32) return;
    int n = i >> 5, o = i & 31;
    g_states[(size_t)n * 128 + l * 32 + o] = tanhf(g_agg[i]);
}

// ---------------- gather z = [states[user], states[item]] --------------------
__global__ void k_gather(const int* __restrict__ ui, const int* __restrict__ vi) {
    int i = blockIdx.x * blockDim.x + threadIdx.x;
    if (i >= B_PAIRS * 256) return;
    int b = i >> 8, o = i & 255;
    int node = (o < 128) ? ui[b] : vi[b];
    g_z[i] = g_states[(size_t)node * 128 + (o & 127)];
}

// ---------------- x-gates GEMM for layer 0 ------------------------------------
__global__ void __launch_bounds__(256)
k_xg(const float* __restrict__ wih, const float* __restrict__ bih,
     const float* __restrict__ bhh) {
    __shared__ __align__(16) float As[32][65];
    __shared__ __align__(16) float Bs[32][65];
    int tid = threadIdx.x;
    int m0 = blockIdx.y * 64, n0 = blockIdx.x * 64;
    int tm = tid >> 4, tn = tid & 15;
    float acc[4][4];
    #pragma unroll
    for (int u = 0; u < 4; u++)
        #pragma unroll
        for (int v = 0; v < 4; v++) acc[u][v] = 0.f;

    for (int k0 = 0; k0 < 256; k0 += 32) {
        for (int i = tid; i < 512; i += 256) {
            int mm = i >> 3, kq = i & 7;
            float4 v = *(const float4*)&g_z[(size_t)(m0 + mm) * 256 + k0 + kq * 4];
            As[kq * 4 + 0][mm] = v.x; As[kq * 4 + 1][mm] = v.y;
            As[kq * 4 + 2][mm] = v.z; As[kq * 4 + 3][mm] = v.w;
        }
        for (int i = tid; i < 512; i += 256) {
            int nn = i >> 3, kq = i & 7;
            float4 v = *(const float4*)&wih[(size_t)(n0 + nn) * 256 + k0 + kq * 4];
            Bs[kq * 4 + 0][nn] = v.x; Bs[kq * 4 + 1][nn] = v.y;
            Bs[kq * 4 + 2][nn] = v.z; Bs[kq * 4 + 3][nn] = v.w;
        }
        __syncthreads();
        #pragma unroll
        for (int kk = 0; kk < 32; kk++) {
            float a[4], b[4];
            #pragma unroll
            for (int u = 0; u < 4; u++) { a[u] = As[kk][tm * 4 + u]; b[u] = Bs[kk][tn * 4 + u]; }
            #pragma unroll
            for (int u = 0; u < 4; u++)
                #pragma unroll
                for (int v = 0; v < 4; v++) acc[u][v] += a[u] * b[v];
        }
        __syncthreads();
    }
    #pragma unroll
    for (int u = 0; u < 4; u++)
        #pragma unroll
        for (int v = 0; v < 4; v++) {
            int rr = n0 + tn * 4 + v;
            g_xg[(size_t)(m0 + tm * 4 + u) * 1024 + rr] = acc[u][v] + bih[rr] + bhh[rr];
        }
}

// ---------------- cluster LSTM scan (64B bulk-copy all-gather) ----------------
// 32 CTAs x 512 threads, cluster=(16,1,1): cluster 0 = layer 0, cluster 1 = layer 1.
// CTA rank k owns h-indices [16k,16k+16); warp w -> j=16k+w. Lane = p*8+s.
// Column mapping (conflict-free contiguous smem): lane s, step q covers
// columns q*32 + s*4 .. +3. Per step each CTA stages its 16 h locally, then
// warp 0 lanes 0..15 issue ONE 64B cp.async.bulk each to the 16 cluster CTAs
// (16 tx-completions per receiver per step instead of 256 scalar messages).
__global__ void __launch_bounds__(512, 1)
k_scan_cluster(const float* __restrict__ wih_g, const float* __restrict__ whh_g,
               const float* __restrict__ bih, const float* __restrict__ bhh) {
    int layer = blockIdx.x >> 4;
    uint32_t crank;
    asm("mov.u32 %0, %%cluster_ctarank;" : "=r"(crank));
    int tid = threadIdx.x;
    int w = tid >> 5, lane = tid & 31;
    int p = lane >> 3, s = lane & 7;
    int j = (int)crank * 16 + w;   // h index 0..255
    int row = p * 256 + j;         // gate row 0..1023

    // weights in registers with interleaved column map: whh[4q+u] = W[row][q*32+s*4+u]
    float whh[32], wih[32];
    {
        const float* WhhP = whh_g + (size_t)layer * 262144 + (size_t)row * 256;
        #pragma unroll
        for (int q = 0; q < 8; q++)
            #pragma unroll
            for (int u = 0; u < 4; u++)
                whh[4 * q + u] = WhhP[q * 32 + s * 4 + u];
    }
    if (layer == 1) {
        const float* WihP = wih_g + (size_t)262144 + (size_t)row * 256;
        #pragma unroll
        for (int q = 0; q < 8; q++)
            #pragma unroll
            for (int u = 0; u < 4; u++)
                wih[4 * q + u] = WihP[q * 32 + s * 4 + u];
    } else {
        #pragma unroll
        for (int c = 0; c < 32; c++) wih[c] = 0.f;
    }
    float bias = 0.f;
    if (layer == 1 && s == 0) bias = bih[1024 + row] + bhh[1024 + row];

    __shared__ __align__(16) float hA[2][256];     // all-gathered own-layer h
    __shared__ __align__(16) float hX[2][256];     // layer1: prefetched h1
    __shared__ __align__(16) float hstage[2][16];  // local 16 h staging (64 B)
    __shared__ __align__(8) unsigned long long barA[2];

    uint32_t bar0 = smem_u32(&barA[0]);
    uint32_t bar1 = smem_u32(&barA[1]);
    if (tid == 0) { mbar_init(bar0, 1); mbar_init(bar1, 1); }
    __syncthreads();
    if (tid == 0) { mbar_arrive_expect(bar0, 1024); mbar_arrive_expect(bar1, 1024); }

    // layer1 prologue: prefetch h1(0)
    if (layer == 1 && tid < 256)
        hX[0][tid] = poll_word(&g_h1p[tid], 1u);
    __syncthreads();
    cluster_sync_();   // expects visible cluster-wide before any bulk copy

    // bulk-copy routes: warp 0 lane k -> peer CTA k, dst = peer hA[buf]+crank*64B
    uint32_t dst0 = 0, dst1 = 0, mb0 = 0, mb1 = 0;
    uint32_t src0 = smem_u32(&hstage[0][0]);
    uint32_t src1 = smem_u32(&hstage[1][0]);
    if (w == 0 && lane < 16) {
        dst0 = mapa_u32(smem_u32(&hA[0][crank * 16]), (uint32_t)lane);
        dst1 = mapa_u32(smem_u32(&hA[1][crank * 16]), (uint32_t)lane);
        mb0  = mapa_u32(bar0, (uint32_t)lane);
        mb1  = mapa_u32(bar1, (uint32_t)lane);
    }

    int ph0 = 0, ph1 = 0;
    float cst = 0.f;

    #pragma unroll 1
    for (int t = 0; t < T_STEPS; t++) {
        int buf = t & 1;
        int pb = (t - 1) & 1;
        float xg = 0.f;
        if (layer == 0 && s == 0)
            xg = __ldg(&g_xg[(size_t)t * 1024 + row]);

        // wait own-layer h(t-1) arrivals; repost expect (race-free: peers can't
        // publish h(t+1) before our own h(t), which follows this repost)
        if (t > 0) {
            if (pb == 0) {
                mbar_wait_cluster(bar0, ph0); ph0 ^= 1;
                if (tid == 0) mbar_arrive_expect(bar0, 1024);
            } else {
                mbar_wait_cluster(bar1, ph1); ph1 ^= 1;
                if (tid == 0) mbar_arrive_expect(bar1, 1024);
            }
        }

        // gate dot products (interleaved column map, conflict-free)
        float acc = 0.f;
        if (layer == 0) {
            if (t > 0) {
                const float4* hp = (const float4*)&hA[pb][0];
                #pragma unroll
                for (int q = 0; q < 8; q++) {
                    float4 h4 = hp[q * 8 + s];
                    acc += whh[4*q] * h4.x + whh[4*q+1] * h4.y
                         + whh[4*q+2] * h4.z + whh[4*q+3] * h4.w;
                }
            }
        } else {
            const float4* xp = (const float4*)&hX[buf][0];
            #pragma unroll
            for (int q = 0; q < 8; q++) {
                float4 h4 = xp[q * 8 + s];
                acc += wih[4*q] * h4.x + wih[4*q+1] * h4.y
                     + wih[4*q+2] * h4.z + wih[4*q+3] * h4.w;
            }
            if (t > 0) {
                const float4* hp = (const float4*)&hA[pb][0];
                #pragma unroll
                for (int q = 0; q < 8; q++) {
                    float4 h4 = hp[q * 8 + s];
                    acc += whh[4*q] * h4.x + whh[4*q+1] * h4.y
                         + whh[4*q+2] * h4.z + whh[4*q+3] * h4.w;
                }
            }
        }
        acc += __shfl_xor_sync(0xffffffffu, acc, 4);
        acc += __shfl_xor_sync(0xffffffffu, acc, 2);
        acc += __shfl_xor_sync(0xffffffffu, acc, 1);

        float gact = 0.f;
        if (s == 0) {
            float gv = acc + bias + xg;
            gact = (p == 2) ? tanhf(gv) : __fdividef(1.f, 1.f + __expf(-gv));
        }
        float gi = __shfl_sync(0xffffffffu, gact, 0);
        float gf = __shfl_sync(0xffffffffu, gact, 8);
        float gg = __shfl_sync(0xffffffffu, gact, 16);
        float go = __shfl_sync(0xffffffffu, gact, 24);

        float h = 0.f;
        if (lane == 0) {
            cst = gf * cst + gi * gg;
            h = go * tanhf(cst);
            hstage[buf][w] = h;                       // local staging
        }
        h = __shfl_sync(0xffffffffu, h, 0);
        if (lane == 16) {                             // L2 publish for next stage
            unsigned long long wrd = ((unsigned long long)(unsigned)(t + 1) << 32)
                                   | (unsigned long long)__float_as_uint(h);
            if (layer == 0)
                asm volatile("st.global.release.gpu.b64 [%0], %1;"
                             :: "l"(&g_h1p[(size_t)t * 256 + j]), "l"(wrd) : "memory");
            else
                asm volatile("st.global.cg.b64 [%0], %1;"
                             :: "l"(&g_h2p[(size_t)t * 256 + j]), "l"(wrd) : "memory");
        }
        // layer1: prefetch h1(t+1) now — layer0 runs ahead, so this is a plain
        // L2 read that overlaps the publish/sync tail instead of the next dot.
        if (layer == 1 && tid < 256 && t + 1 < T_STEPS) {
            float v = poll_word(&g_h1p[(size_t)(t + 1) * 256 + tid], (unsigned)(t + 2));
            hX[buf ^ 1][tid] = v;
        }
        __syncthreads();   // hstage complete (also orders hX for next step)

        // 16 bulk copies: this CTA's 64B h-segment -> every cluster CTA
        if (w == 0) {
            fence_proxy_async_cta();
            if (lane < 16)
                dsmem_bulk64(buf ? dst1 : dst0, buf ? src1 : src0, buf ? mb1 : mb0);
        }
    }
    cluster_sync_();   // no CTA exits while peers' bulk copies may be in flight
}

// ---------------- fallback L2-tag scan (proven) --------------------------------
__global__ void __launch_bounds__(512, 1)
k_scan_l2(const float* __restrict__ wih_g, const float* __restrict__ whh_g,
          const float* __restrict__ bih, const float* __restrict__ bhh) {
    int blk = blockIdx.x;
    int layer = blk >> 4;
    int k = blk & 15;
    int tid = threadIdx.x;
    int w = tid >> 5, lane = tid & 31;
    int p = lane >> 3, s = lane & 7;
    int j = k * 16 + w;
    int row = p * 256 + j;

    float wih[32], whh[32];
    {
        const float* WhhP = whh_g + (size_t)layer * 262144 + (size_t)row * 256 + s * 32;
        #pragma unroll
        for (int c = 0; c < 32; c++) whh[c] = WhhP[c];
    }
    if (layer == 1) {
        const float* WihP = wih_g + (size_t)262144 + (size_t)row * 256 + s * 32;
        #pragma unroll
        for (int c = 0; c < 32; c++) wih[c] = WihP[c];
    } else {
        #pragma unroll
        for (int c = 0; c < 32; c++) wih[c] = 0.f;
    }
    float bias = 0.f;
    if (layer == 1 && s == 0) bias = bih[1024 + row] + bhh[1024 + row];

    unsigned long long* outp = (layer == 0) ? g_h1p : g_h2p;
    __shared__ __align__(16) float hA[2][288];
    __shared__ __align__(16) float hB[2][288];
    float cst = 0.f;

    #pragma unroll 1
    for (int t = 0; t < T_STEPS; t++) {
        int buf = t & 1;
        float xg = 0.f;
        if (layer == 0 && s == 0)
            xg = __ldg(&g_xg[(size_t)t * 1024 + row]);

        if (layer == 0) {
            if (t > 0 && tid < 256) {
                float v = poll_word(&g_h1p[(size_t)(t - 1) * 256 + tid], (unsigned)t);
                hA[buf][(tid >> 5) * 36 + (tid & 31)] = v;
            }
        } else {
            if (tid < 256) {
                float v = poll_word(&g_h1p[(size_t)t * 256 + tid], (unsigned)(t + 1));
                hA[buf][(tid >> 5) * 36 + (tid & 31)] = v;
            } else if (t > 0) {
                int c = tid - 256;
                float v = poll_word(&g_h2p[(size_t)(t - 1) * 256 + c], (unsigned)t);
                hB[buf][(c >> 5) * 36 + (c & 31)] = v;
            }
        }
        __syncthreads();

        float acc = 0.f;
        if (layer == 0) {
            if (t > 0) {
                const float4* hp = (const float4*)&hA[buf][s * 36];
                #pragma unroll
                for (int q = 0; q < 8; q++) {
                    float4 h4 = hp[q];
                    acc += whh[4*q] * h4.x + whh[4*q+1] * h4.y
                         + whh[4*q+2] * h4.z + whh[4*q+3] * h4.w;
                }
            }
        } else {
            const float4* xp = (const float4*)&hA[buf][s * 36];
            #pragma unroll
            for (int q = 0; q < 8; q++) {
                float4 h4 = xp[q];
                acc += wih[4*q] * h4.x + wih[4*q+1] * h4.y
                     + wih[4*q+2] * h4.z + wih[4*q+3] * h4.w;
            }
            if (t > 0) {
                const float4* hp = (const float4*)&hB[buf][s * 36];
                #pragma unroll
                for (int q = 0; q < 8; q++) {
                    float4 h4 = hp[q];
                    acc += whh[4*q] * h4.x + whh[4*q+1] * h4.y
                         + whh[4*q+2] * h4.z + whh[4*q+3] * h4.w;
                }
            }
        }
        acc += __shfl_xor_sync(0xffffffffu, acc, 4);
        acc += __shfl_xor_sync(0xffffffffu, acc, 2);
        acc += __shfl_xor_sync(0xffffffffu, acc, 1);

        float gact = 0.f;
        if (s == 0) {
            float gv = acc + bias + xg;
            gact = (p == 2) ? tanhf(gv) : __fdividef(1.f, 1.f + __expf(-gv));
        }
        float gi = __shfl_sync(0xffffffffu, gact, 0);
        float gf = __shfl_sync(0xffffffffu, gact, 8);
        float gg = __shfl_sync(0xffffffffu, gact, 16);
        float go = __shfl_sync(0xffffffffu, gact, 24);

        if (lane == 0) {
            cst = gf * cst + gi * gg;
            float h = go * tanhf(cst);
            publish_word(&outp[(size_t)t * 256 + j], h, (unsigned)(t + 1));
        }
    }
}

// ---------------- final MLP head ----------------------------------------------
__global__ void k_head(const float* __restrict__ l1w, const float* __restrict__ l1b,
                       const float* __restrict__ l2w, const float* __restrict__ l2b,
                       float* __restrict__ out) {
    int b = blockIdx.x;
    int tid = threadIdx.x;  // 256 threads
    int w = tid >> 5, lane = tid & 31;
    __shared__ __align__(16) float hs[256];
    __shared__ float rs[128];
    __shared__ float part[8];

    hs[tid] = __uint_as_float((unsigned)(g_h2p[(size_t)b * 256 + tid] & 0xffffffffull));
    __syncthreads();

    for (int q = 0; q < 16; q++) {
        int jrow = w * 16 + q;
        const float4* wp = (const float4*)(l1w + (size_t)jrow * 256 + lane * 8);
        float4 wa = wp[0], wb = wp[1];
        const float4* hp = (const float4*)(hs + lane * 8);
        float4 haa = hp[0], hbb = hp[1];
        float acc = wa.x * haa.x + wa.y * haa.y + wa.z * haa.z + wa.w * haa.w
                  + wb.x * hbb.x + wb.y * hbb.y + wb.z * hbb.z + wb.w * hbb.w;
        #pragma unroll
        for (int sft = 16; sft > 0; sft >>= 1)
            acc += __shfl_xor_sync(0xffffffffu, acc, sft);
        if (lane == 0) rs[jrow] = fmaxf(acc + l1b[jrow], 0.f);
    }
    __syncthreads();

    float v = (tid < 128) ? rs[tid] * l2w[tid] : 0.f;
    #pragma unroll
    for (int sft = 16; sft > 0; sft >>= 1)
        v += __shfl_xor_sync(0xffffffffu, v, sft);
    if (lane == 0) part[w] = v;
    __syncthreads();
    if (tid == 0) {
        float sum = 0.f;
        #pragma unroll
        for (int i = 0; i < 8; i++) sum += part[i];
        out[b] = sum + l2b[0];
    }
}

// ---------------- launch --------------------------------------------------------
extern "C" void kernel_launch(void* const* d_in, const int* in_sizes, int n_in,
                              void* d_out, int out_size) {
    const float* x     = (const float*)d_in[0];
    const int*   ei    = (const int*)  d_in[1];
    const int*   et    = (const int*)  d_in[2];
    const int*   ui    = (const int*)  d_in[3];
    const int*   vi    = (const int*)  d_in[4];
    const float* basis = (const float*)d_in[5];
    const float* comp  = (const float*)d_in[6];
    const float* root  = (const float*)d_in[7];
    const float* cbias = (const float*)d_in[8];
    const float* w_ih  = (const float*)d_in[9];
    const float* w_hh  = (const float*)d_in[10];
    const float* b_ih  = (const float*)d_in[11];
    const float* b_hh  = (const float*)d_in[12];
    const float* l1w   = (const float*)d_in[13];
    const float* l1b   = (const float*)d_in[14];
    const float* l2w   = (const float*)d_in[15];
    const float* l2b   = (const float*)d_in[16];
    float* out = (float*)d_out;

    k_init<<<(N_NODES * R_REL + 255) / 256, 256>>>();
    k_zerotags<<<(T_STEPS * 256 + 255) / 256, 256>>>();
    k_count<<<(E_EDGES + 255) / 256, 256>>>(ei, et);
    k_weff<<<(L_LAYERS * 32 * 192 + 255) / 256, 256>>>(basis, comp, root);

    for (int l = 0; l < L_LAYERS; l++) {
        k_transform<<<N_NODES / 32, 192>>>(x, cbias + l * 32, l);
        k_edge<<<((size_t)E_EDGES * 8) / 256, 256>>>(ei, et);
        k_tanh<<<(N_NODES * 32) / 256, 256>>>(l);
    }

    k_gather<<<(B_PAIRS * 256) / 256, 256>>>(ui, vi);
    k_xg<<<dim3(16, 64), 256>>>(w_ih, b_ih, b_hh);

    // cluster scan (16-CTA non-portable clusters) with occupancy pre-check;
    // fallback to proven L2-tag scan.
    bool launched = false;
    cudaError_t arc = cudaFuncSetAttribute(
        k_scan_cluster, cudaFuncAttributeNonPortableClusterSizeAllowed, 1);
    if (arc == cudaSuccess) {
        cudaLaunchConfig_t cfg = {};
        cfg.gridDim = dim3(32, 1, 1);
        cfg.blockDim = dim3(512, 1, 1);
        cfg.dynamicSmemBytes = 0;
        cudaLaunchAttribute attrs[1];
        attrs[0].id = cudaLaunchAttributeClusterDimension;
        attrs[0].val.clusterDim.x = 16;
        attrs[0].val.clusterDim.y = 1;
        attrs[0].val.clusterDim.z = 1;
        cfg.attrs = attrs;
        cfg.numAttrs = 1;
        int nclus = 0;
        cudaError_t qrc = cudaOccupancyMaxActiveClusters(&nclus, k_scan_cluster, &cfg);
        if (qrc == cudaSuccess && nclus >= 2) {
            if (cudaLaunchKernelEx(&cfg, k_scan_cluster, w_ih, w_hh, b_ih, b_hh)
                == cudaSuccess)
                launched = true;
        }
    }
    if (!launched)
        k_scan_l2<<<32, 512>>>(w_ih, w_hh, b_ih, b_hh);

    k_head<<<B_PAIRS, 256>>>(l1w, l1b, l2w, l2b, out);
}

// round 9
// speedup vs baseline: 2.1185x; 1.0130x over previous
#include <cuda_runtime.h>
#include <math.h>
#include <stdint.h>
#include <stddef.h>

#define N_NODES 131072
#define E_EDGES 2097152
#define B_PAIRS 4096
#define R_REL   5
#define L_LAYERS 4
#define T_STEPS 4096

// ---------------- device scratch (static globals; no runtime allocation) ----
static __device__ float g_relfeat[(size_t)N_NODES * R_REL * 32];  // 80 MB
static __device__ float g_agg[(size_t)N_NODES * 32];              // 16 MB
static __device__ float g_states[(size_t)N_NODES * 128];          // 64 MB
static __device__ int   g_cnt[(size_t)N_NODES * R_REL];           // 2.5 MB
static __device__ float g_weff[L_LAYERS * 32 * 192];              // 96 KB
static __device__ float g_z [(size_t)B_PAIRS * 256];              // 4 MB
static __device__ float g_xg[(size_t)T_STEPS * 1024];             // 16 MB
static __device__ unsigned long long g_h1p[(size_t)T_STEPS * 256];  // packed (h, tag)
static __device__ unsigned long long g_h2p[(size_t)T_STEPS * 256];  // packed (h, tag)

// ---------------- packed publish/poll: scalar b64 + acquire/release ---------
// EMPIRICALLY LOAD-BEARING: weak b64 (.cv/.cg) and v2.u32 variants both
// produced rel_err ~0.3 (stale payload visible with fresh tag). The morally
// strong acquire/release.gpu accesses are required for cross-SM single-copy
// atomicity + ordering of the packed (h, tag) word. Do not weaken again.
__device__ __forceinline__ float poll_word(const unsigned long long* p, unsigned tag) {
    unsigned long long w;
    do {
        asm volatile("ld.global.acquire.gpu.b64 %0, [%1];"
                     : "=l"(w) : "l"(p) : "memory");
    } while ((unsigned)(w >> 32) != tag);
    return __uint_as_float((unsigned)(w & 0xffffffffull));
}
__device__ __forceinline__ void publish_word(unsigned long long* p, float h, unsigned tag) {
    unsigned long long w = ((unsigned long long)tag << 32)
                         | (unsigned long long)__float_as_uint(h);
    asm volatile("st.global.release.gpu.b64 [%0], %1;"
                 :: "l"(p), "l"(w) : "memory");
}

// ---------------- init: zero counts ------------------------------------------
__global__ void k_init() {
    int i = blockIdx.x * blockDim.x + threadIdx.x;
    if (i < N_NODES * R_REL) g_cnt[i] = 0;
}

// ---------------- zero the packed tag buffers (graph-replay safe) ------------
__global__ void k_zerotags() {
    size_t i = (size_t)blockIdx.x * blockDim.x + threadIdx.x;
    if (i < (size_t)T_STEPS * 256) {
        g_h1p[i] = 0ull;
        g_h2p[i] = 0ull;
    }
}

// ---------------- per-(dst,rel) edge counts ----------------------------------
__global__ void k_count(const int* __restrict__ ei, const int* __restrict__ et) {
    int e = blockIdx.x * blockDim.x + threadIdx.x;
    if (e >= E_EDGES) return;
    int dst = ei[E_EDGES + e];
    int r   = et[e];
    atomicAdd(&g_cnt[(size_t)dst * R_REL + r], 1);
}

// ---------------- effective relation weights ---------------------------------
__global__ void k_weff(const float* __restrict__ basis,
                       const float* __restrict__ comp,
                       const float* __restrict__ root) {
    int idx = blockIdx.x * blockDim.x + threadIdx.x;
    if (idx >= L_LAYERS * 32 * 192) return;
    int l = idx / (32 * 192);
    int rem = idx % (32 * 192);
    int i = rem / 192;
    int o = rem % 192;
    int r = o / 32, j = o % 32;
    float v;
    if (r < R_REL) {
        v = 0.f;
        #pragma unroll
        for (int b = 0; b < 4; b++)
            v += comp[(l * R_REL + r) * 4 + b] * basis[(((size_t)l * 4 + b) * 32 + i) * 32 + j];
    } else {
        v = root[((size_t)l * 32 + i) * 32 + j];
    }
    g_weff[idx] = v;
}

// ---------------- node transform ---------------------------------------------
__global__ void k_transform(const float* __restrict__ x,
                            const float* __restrict__ cbias, int l) {
    __shared__ __align__(16) float hs[32][32];
    int n0 = blockIdx.x * 32;
    int tid = threadIdx.x;  // 0..191

    for (int i = tid; i < 1024; i += 192) {
        int m = i >> 5, c = i & 31;
        float v;
        if (l == 0) v = x[(size_t)(n0 + m) * 32 + c];
        else        v = g_states[(size_t)(n0 + m) * 128 + (l - 1) * 32 + c];
        hs[m][c] = v;
    }
    float wreg[32];
    const float* W = g_weff + l * 32 * 192;
    #pragma unroll
    for (int i = 0; i < 32; i++) wreg[i] = W[i * 192 + tid];
    __syncthreads();

    int r = tid / 32, o = tid % 32;
    float bias = (r == 5) ? cbias[o] : 0.f;

    for (int m = 0; m < 32; m++) {
        const float4* hp = (const float4*)hs[m];
        float acc = 0.f;
        #pragma unroll
        for (int i4 = 0; i4 < 8; i4++) {
            float4 h4 = hp[i4];
            acc += h4.x * wreg[i4 * 4 + 0];
            acc += h4.y * wreg[i4 * 4 + 1];
            acc += h4.z * wreg[i4 * 4 + 2];
            acc += h4.w * wreg[i4 * 4 + 3];
        }
        if (r < R_REL)
            g_relfeat[((size_t)(n0 + m) * R_REL + r) * 32 + o] = acc;
        else
            g_agg[(size_t)(n0 + m) * 32 + o] = acc + bias;
    }
}

// ---------------- edge aggregation: 8 lanes/edge, vector reductions ----------
__global__ void k_edge(const int* __restrict__ ei, const int* __restrict__ et) {
    int gid = blockIdx.x * blockDim.x + threadIdx.x;
    int e = gid >> 3;
    int q = gid & 7;
    if (e >= E_EDGES) return;
    int src = ei[e];
    int dst = ei[E_EDGES + e];
    int r   = et[e];
    int cnt = g_cnt[(size_t)dst * R_REL + r];
    float norm = 1.0f / (float)(cnt < 1 ? 1 : cnt);
    float4 v = *(const float4*)&g_relfeat[((size_t)src * R_REL + r) * 32 + q * 4];
    float* p = &g_agg[(size_t)dst * 32 + q * 4];
    asm volatile("red.global.add.v4.f32 [%0], {%1,%2,%3,%4};"
                 :: "l"(p), "f"(v.x * norm), "f"(v.y * norm),
                    "f"(v.z * norm), "f"(v.w * norm)
                 : "memory");
}

// ---------------- tanh into concat states ------------------------------------
__global__ void k_tanh(int l) {
    int i = blockIdx.x * blockDim.x + threadIdx.x;
    if (i >= N_NODES * 32) return;
    int n = i >> 5, o = i & 31;
    g_states[(size_t)n * 128 + l * 32 + o] = tanhf(g_agg[i]);
}

// ---------------- gather z = [states[user], states[item]] --------------------
__global__ void k_gather(const int* __restrict__ ui, const int* __restrict__ vi) {
    int i = blockIdx.x * blockDim.x + threadIdx.x;
    if (i >= B_PAIRS * 256) return;
    int b = i >> 8, o = i & 255;
    int node = (o < 128) ? ui[b] : vi[b];
    g_z[i] = g_states[(size_t)node * 128 + (o & 127)];
}

// ---------------- x-gates GEMM for layer 0 ------------------------------------
__global__ void __launch_bounds__(256)
k_xg(const float* __restrict__ wih, const float* __restrict__ bih,
     const float* __restrict__ bhh) {
    __shared__ __align__(16) float As[32][65];
    __shared__ __align__(16) float Bs[32][65];
    int tid = threadIdx.x;
    int m0 = blockIdx.y * 64, n0 = blockIdx.x * 64;
    int tm = tid >> 4, tn = tid & 15;
    float acc[4][4];
    #pragma unroll
    for (int u = 0; u < 4; u++)
        #pragma unroll
        for (int v = 0; v < 4; v++) acc[u][v] = 0.f;

    for (int k0 = 0; k0 < 256; k0 += 32) {
        for (int i = tid; i < 512; i += 256) {
            int mm = i >> 3, kq = i & 7;
            float4 v = *(const float4*)&g_z[(size_t)(m0 + mm) * 256 + k0 + kq * 4];
            As[kq * 4 + 0][mm] = v.x; As[kq * 4 + 1][mm] = v.y;
            As[kq * 4 + 2][mm] = v.z; As[kq * 4 + 3][mm] = v.w;
        }
        for (int i = tid; i < 512; i += 256) {
            int nn = i >> 3, kq = i & 7;
            float4 v = *(const float4*)&wih[(size_t)(n0 + nn) * 256 + k0 + kq * 4];
            Bs[kq * 4 + 0][nn] = v.x; Bs[kq * 4 + 1][nn] = v.y;
            Bs[kq * 4 + 2][nn] = v.z; Bs[kq * 4 + 3][nn] = v.w;
        }
        __syncthreads();
        #pragma unroll
        for (int kk = 0; kk < 32; kk++) {
            float a[4], b[4];
            #pragma unroll
            for (int u = 0; u < 4; u++) { a[u] = As[kk][tm * 4 + u]; b[u] = Bs[kk][tn * 4 + u]; }
            #pragma unroll
            for (int u = 0; u < 4; u++)
                #pragma unroll
                for (int v = 0; v < 4; v++) acc[u][v] += a[u] * b[v];
        }
        __syncthreads();
    }
    #pragma unroll
    for (int u = 0; u < 4; u++)
        #pragma unroll
        for (int v = 0; v < 4; v++) {
            int rr = n0 + tn * 4 + v;
            g_xg[(size_t)(m0 + tm * 4 + u) * 1024 + rr] = acc[u][v] + bih[rr] + bhh[rr];
        }
}

// ---------------- persistent 2-layer LSTM scan (L2 tag words) -----------------
// 64 CTAs x 256 threads. Blocks 0..31 = layer 0, 32..63 = layer 1.
// CTA k owns h-indices [8k, 8k+8); warp w (0..7) -> j = 8k+w (2 warps/SMSP).
// Lane = p*8+s: gate p (i,f,g,o), 32-col slice s. Weights in registers.
// Publish: packed (h, t+1) release.gpu.b64; poll: acquire.gpu.b64 tag match.
// Layer 0 runs ahead unboundedly, so layer 1's h1(t) poll is a warm L2 read;
// only its own h2(t-1) is a true recurrence wait.
__global__ void __launch_bounds__(256, 1)
k_scan(const float* __restrict__ wih_g, const float* __restrict__ whh_g,
       const float* __restrict__ bih, const float* __restrict__ bhh) {
    int blk = blockIdx.x;
    int layer = blk >> 5;
    int k = blk & 31;
    int tid = threadIdx.x;
    int w = tid >> 5, lane = tid & 31;
    int p = lane >> 3, s = lane & 7;
    int j = k * 8 + w;           // h index 0..255
    int row = p * 256 + j;       // gate row 0..1023

    float wih[32], whh[32];
    {
        const float* WhhP = whh_g + (size_t)layer * 262144 + (size_t)row * 256 + s * 32;
        #pragma unroll
        for (int c = 0; c < 32; c++) whh[c] = WhhP[c];
    }
    if (layer == 1) {
        const float* WihP = wih_g + (size_t)262144 + (size_t)row * 256 + s * 32;
        #pragma unroll
        for (int c = 0; c < 32; c++) wih[c] = WihP[c];
    } else {
        #pragma unroll
        for (int c = 0; c < 32; c++) wih[c] = 0.f;
    }
    float bias = 0.f;
    if (layer == 1 && s == 0) bias = bih[1024 + row] + bhh[1024 + row];

    unsigned long long* outp = (layer == 0) ? g_h1p : g_h2p;
    __shared__ __align__(16) float hA[2][288];   // own-layer h(t-1)
    __shared__ __align__(16) float hX[2][288];   // layer1: h1(t)
    float cst = 0.f;

    #pragma unroll 1
    for (int t = 0; t < T_STEPS; t++) {
        int buf = t & 1;
        float xg = 0.f;
        if (layer == 0 && s == 0)
            xg = __ldg(&g_xg[(size_t)t * 1024 + row]);

        // ---- poll phase: 256 threads fill smem with required h vectors ----
        int pos = (tid >> 5) * 36 + (tid & 31);
        if (layer == 0) {
            if (t > 0)
                hA[buf][pos] = poll_word(&g_h1p[(size_t)(t - 1) * 256 + tid], (unsigned)t);
        } else {
            hX[buf][pos] = poll_word(&g_h1p[(size_t)t * 256 + tid], (unsigned)(t + 1));
            if (t > 0)
                hA[buf][pos] = poll_word(&g_h2p[(size_t)(t - 1) * 256 + tid], (unsigned)t);
        }
        __syncthreads();

        // ---- gate dot products: 4 independent accumulator chains ----
        float a0 = 0.f, a1 = 0.f, a2 = 0.f, a3 = 0.f;
        if (layer == 0) {
            if (t > 0) {
                const float4* hp = (const float4*)&hA[buf][s * 36];
                #pragma unroll
                for (int q = 0; q < 8; q++) {
                    float4 h4 = hp[q];
                    a0 += whh[4*q]   * h4.x;
                    a1 += whh[4*q+1] * h4.y;
                    a2 += whh[4*q+2] * h4.z;
                    a3 += whh[4*q+3] * h4.w;
                }
            }
        } else {
            const float4* xp = (const float4*)&hX[buf][s * 36];
            #pragma unroll
            for (int q = 0; q < 8; q++) {
                float4 h4 = xp[q];
                a0 += wih[4*q]   * h4.x;
                a1 += wih[4*q+1] * h4.y;
                a2 += wih[4*q+2] * h4.z;
                a3 += wih[4*q+3] * h4.w;
            }
            if (t > 0) {
                const float4* hp = (const float4*)&hA[buf][s * 36];
                #pragma unroll
                for (int q = 0; q < 8; q++) {
                    float4 h4 = hp[q];
                    a0 += whh[4*q]   * h4.x;
                    a1 += whh[4*q+1] * h4.y;
                    a2 += whh[4*q+2] * h4.z;
                    a3 += whh[4*q+3] * h4.w;
                }
            }
        }
        float acc = (a0 + a1) + (a2 + a3);
        acc += __shfl_xor_sync(0xffffffffu, acc, 4);
        acc += __shfl_xor_sync(0xffffffffu, acc, 2);
        acc += __shfl_xor_sync(0xffffffffu, acc, 1);

        float gact = 0.f;
        if (s == 0) {
            float gv = acc + bias + xg;
            gact = (p == 2) ? tanhf(gv) : __fdividef(1.f, 1.f + __expf(-gv));
        }
        float gi = __shfl_sync(0xffffffffu, gact, 0);
        float gf = __shfl_sync(0xffffffffu, gact, 8);
        float gg = __shfl_sync(0xffffffffu, gact, 16);
        float go = __shfl_sync(0xffffffffu, gact, 24);

        if (lane == 0) {
            cst = gf * cst + gi * gg;
            float h = go * tanhf(cst);
            publish_word(&outp[(size_t)t * 256 + j], h, (unsigned)(t + 1));
        }
    }
}

// ---------------- final MLP head ----------------------------------------------
__global__ void k_head(const float* __restrict__ l1w, const float* __restrict__ l1b,
                       const float* __restrict__ l2w, const float* __restrict__ l2b,
                       float* __restrict__ out) {
    int b = blockIdx.x;
    int tid = threadIdx.x;  // 256 threads
    int w = tid >> 5, lane = tid & 31;
    __shared__ __align__(16) float hs[256];
    __shared__ float rs[128];
    __shared__ float part[8];

    hs[tid] = __uint_as_float((unsigned)(g_h2p[(size_t)b * 256 + tid] & 0xffffffffull));
    __syncthreads();

    for (int q = 0; q < 16; q++) {
        int jrow = w * 16 + q;
        const float4* wp = (const float4*)(l1w + (size_t)jrow * 256 + lane * 8);
        float4 wa = wp[0], wb = wp[1];
        const float4* hp = (const float4*)(hs + lane * 8);
        float4 haa = hp[0], hbb = hp[1];
        float acc = wa.x * haa.x + wa.y * haa.y + wa.z * haa.z + wa.w * haa.w
                  + wb.x * hbb.x + wb.y * hbb.y + wb.z * hbb.z + wb.w * hbb.w;
        #pragma unroll
        for (int sft = 16; sft > 0; sft >>= 1)
            acc += __shfl_xor_sync(0xffffffffu, acc, sft);
        if (lane == 0) rs[jrow] = fmaxf(acc + l1b[jrow], 0.f);
    }
    __syncthreads();

    float v = (tid < 128) ? rs[tid] * l2w[tid] : 0.f;
    #pragma unroll
    for (int sft = 16; sft > 0; sft >>= 1)
        v += __shfl_xor_sync(0xffffffffu, v, sft);
    if (lane == 0) part[w] = v;
    __syncthreads();
    if (tid == 0) {
        float sum = 0.f;
        #pragma unroll
        for (int i = 0; i < 8; i++) sum += part[i];
        out[b] = sum + l2b[0];
    }
}

// ---------------- launch --------------------------------------------------------
extern "C" void kernel_launch(void* const* d_in, const int* in_sizes, int n_in,
                              void* d_out, int out_size) {
    const float* x     = (const float*)d_in[0];
    const int*   ei    = (const int*)  d_in[1];
    const int*   et    = (const int*)  d_in[2];
    const int*   ui    = (const int*)  d_in[3];
    const int*   vi    = (const int*)  d_in[4];
    const float* basis = (const float*)d_in[5];
    const float* comp  = (const float*)d_in[6];
    const float* root  = (const float*)d_in[7];
    const float* cbias = (const float*)d_in[8];
    const float* w_ih  = (const float*)d_in[9];
    const float* w_hh  = (const float*)d_in[10];
    const float* b_ih  = (const float*)d_in[11];
    const float* b_hh  = (const float*)d_in[12];
    const float* l1w   = (const float*)d_in[13];
    const float* l1b   = (const float*)d_in[14];
    const float* l2w   = (const float*)d_in[15];
    const float* l2b   = (const float*)d_in[16];
    float* out = (float*)d_out;

    k_init<<<(N_NODES * R_REL + 255) / 256, 256>>>();
    k_zerotags<<<(T_STEPS * 256 + 255) / 256, 256>>>();
    k_count<<<(E_EDGES + 255) / 256, 256>>>(ei, et);
    k_weff<<<(L_LAYERS * 32 * 192 + 255) / 256, 256>>>(basis, comp, root);

    for (int l = 0; l < L_LAYERS; l++) {
        k_transform<<<N_NODES / 32, 192>>>(x, cbias + l * 32, l);
        k_edge<<<((size_t)E_EDGES * 8) / 256, 256>>>(ei, et);
        k_tanh<<<(N_NODES * 32) / 256, 256>>>(l);
    }

    k_gather<<<(B_PAIRS * 256) / 256, 256>>>(ui, vi);
    k_xg<<<dim3(16, 64), 256>>>(w_ih, b_ih, b_hh);
    k_scan<<<64, 256>>>(w_ih, w_hh, b_ih, b_hh);
    k_head<<<B_PAIRS, 256>>>(l1w, l1b, l2w, l2b, out);
}